// round 2
// baseline (speedup 1.0000x reference)
#include <cuda_runtime.h>
#include <cuda_bf16.h>
#include <math.h>

// Problem constants
#define NN   50000
#define EE   800000
#define FIN  128
#define D1   256
#define H1   8
#define C1   32
#define NOUT 40

// ---------------- static scratch (no allocation allowed) ----------------
__device__ __align__(256) float g_q1[NN * D1];
__device__ __align__(256) float g_k1[NN * D1];
__device__ __align__(256) float g_v1[NN * D1];
__device__ __align__(256) float g_s1[NN * D1];
__device__ __align__(256) float g_agg1[NN * D1];
__device__ __align__(256) float g_h[NN * D1];
__device__ __align__(256) float g_ea1[EE * H1];
__device__ __align__(256) float g_asum1[NN * H1];

__device__ __align__(256) float g_q2[NN * NOUT];
__device__ __align__(256) float g_k2[NN * NOUT];
__device__ __align__(256) float g_v2[NN * NOUT];
__device__ __align__(256) float g_s2[NN * NOUT];
__device__ __align__(256) float g_agg2[NN * NOUT];
__device__ __align__(256) float g_ea2[EE];
__device__ __align__(256) float g_asum2[NN];

__device__ __align__(256) int g_esrc[EE];
__device__ __align__(256) int g_edst[EE];
__device__ int g_is32;     // 1 if edge_index is int32, 0 if int64
__device__ int g_deg[NN];
__device__ __align__(256) int g_rowptr[NN + 1];
__device__ int g_wp[NN];
__device__ __align__(256) int g_csrsrc[EE];

static inline int cdiv(int a, int b) { return (a + b - 1) / b; }

// ---------------- edge dtype detection + conversion ----------------
__global__ void k_flag_zero() { g_is32 = 0; }

// Probe the first 2*e int32 words (in-bounds for both dtypes).
// int64 view: words [2i, 2i+1] = (low, high) of src[i]; high always 0.
// int32 view: odd words are real node indices (~never all zero over 800k).
__global__ void k_detect(const int* __restrict__ w, int e) {
    int i = blockIdx.x * blockDim.x + threadIdx.x;
    if (i < e) {
        if (w[2 * i + 1] != 0) g_is32 = 1;  // benign race: all writers write 1
    }
}

__global__ void k_convert(const void* __restrict__ ei, int e) {
    int i = blockIdx.x * blockDim.x + threadIdx.x;
    if (i >= e) return;
    if (g_is32) {
        const int* p = (const int*)ei;
        g_esrc[i] = p[i];
        g_edst[i] = p[e + i];
    } else {
        const long long* p = (const long long*)ei;
        g_esrc[i] = (int)p[i];
        g_edst[i] = (int)p[e + i];
    }
}

// ---------------- CSR build ----------------
__global__ void k_zero_deg(int n) {
    int i = blockIdx.x * blockDim.x + threadIdx.x;
    if (i < n) g_deg[i] = 0;
}

__global__ void k_hist(int e) {
    int i = blockIdx.x * blockDim.x + threadIdx.x;
    if (i < e) atomicAdd(&g_deg[g_edst[i]], 1);
}

// single-block exclusive scan over N+1 entries
__global__ void k_scan(int n) {
    __shared__ int sh[1024];
    int tid = threadIdx.x;
    int carry = 0;
    for (int base = 0; base <= n; base += 1024) {
        int idx = base + tid;
        int v = (idx < n) ? g_deg[idx] : 0;
        sh[tid] = v;
        __syncthreads();
        #pragma unroll
        for (int off = 1; off < 1024; off <<= 1) {
            int t = (tid >= off) ? sh[tid - off] : 0;
            __syncthreads();
            sh[tid] += t;
            __syncthreads();
        }
        int incl = sh[tid];
        if (idx <= n) g_rowptr[idx] = carry + incl - v;
        carry += sh[1023];
        __syncthreads();
    }
}

__global__ void k_copy_wp(int n) {
    int i = blockIdx.x * blockDim.x + threadIdx.x;
    if (i < n) g_wp[i] = g_rowptr[i];
}

__global__ void k_scatter(int e) {
    int i = blockIdx.x * blockDim.x + threadIdx.x;
    if (i < e) {
        int d = g_edst[i];
        int pos = atomicAdd(&g_wp[d], 1);
        g_csrsrc[pos] = g_esrc[i];
    }
}

// ---------------- tiled fp32 GEMM: C[M,Nc] = A[M,K] @ W[K,Nc] + bias ----------------
template <int BM, int BN, int BK, int TM, int TN>
__global__ void __launch_bounds__(256) k_gemm_bias(
    const float* __restrict__ A, const float* __restrict__ W,
    const float* __restrict__ bias, float* __restrict__ C,
    int M, int K, int Nc)
{
    static_assert((BM / TM) * (BN / TN) == 256, "256 threads");
    __shared__ float As[BK][BM];
    __shared__ float Ws[BK][BN];

    const int tid = threadIdx.x;
    const int m0 = blockIdx.x * BM;
    const int n0 = blockIdx.y * BN;
    const int tx = tid % (BN / TN);
    const int ty = tid / (BN / TN);

    float acc[TM][TN];
    #pragma unroll
    for (int i = 0; i < TM; i++)
        #pragma unroll
        for (int j = 0; j < TN; j++) acc[i][j] = 0.f;

    constexpr int A_LD = (BM * BK) / (256 * 4);
    constexpr int W_LD = (BN * BK) / (256 * 4);

    for (int k0 = 0; k0 < K; k0 += BK) {
        #pragma unroll
        for (int i = 0; i < A_LD; i++) {
            int q = tid + i * 256;
            int r = q / (BK / 4);
            int c4 = q % (BK / 4);
            int grow = m0 + r;
            float4 v = make_float4(0.f, 0.f, 0.f, 0.f);
            if (grow < M) v = *(const float4*)&A[(size_t)grow * K + k0 + c4 * 4];
            As[c4 * 4 + 0][r] = v.x;
            As[c4 * 4 + 1][r] = v.y;
            As[c4 * 4 + 2][r] = v.z;
            As[c4 * 4 + 3][r] = v.w;
        }
        #pragma unroll
        for (int i = 0; i < W_LD; i++) {
            int q = tid + i * 256;
            int kk = q / (BN / 4);
            int c4 = q % (BN / 4);
            int gn = n0 + c4 * 4;
            float4 v = make_float4(0.f, 0.f, 0.f, 0.f);
            if (gn < Nc) v = *(const float4*)&W[(size_t)(k0 + kk) * Nc + gn];
            *(float4*)&Ws[kk][c4 * 4] = v;
        }
        __syncthreads();

        #pragma unroll
        for (int kk = 0; kk < BK; kk++) {
            float a[TM], b[TN];
            #pragma unroll
            for (int i = 0; i < TM; i++) a[i] = As[kk][ty * TM + i];
            #pragma unroll
            for (int j = 0; j < TN; j++) b[j] = Ws[kk][tx * TN + j];
            #pragma unroll
            for (int i = 0; i < TM; i++)
                #pragma unroll
                for (int j = 0; j < TN; j++)
                    acc[i][j] = fmaf(a[i], b[j], acc[i][j]);
        }
        __syncthreads();
    }

    #pragma unroll
    for (int i = 0; i < TM; i++) {
        int grow = m0 + ty * TM + i;
        if (grow >= M) continue;
        #pragma unroll
        for (int j = 0; j < TN; j++) {
            int gcol = n0 + tx * TN + j;
            if (gcol < Nc)
                C[(size_t)grow * Nc + gcol] = acc[i][j] + bias[gcol];
        }
    }
}

// ---------------- layer 1 edge passes (warp per dst node) ----------------
__global__ void __launch_bounds__(256) k_attn1(
    const float* __restrict__ q, const float* __restrict__ k, int n)
{
    int warp = (blockIdx.x * blockDim.x + threadIdx.x) >> 5;
    int lane = threadIdx.x & 31;
    if (warp >= n) return;
    int s0 = g_rowptr[warp], s1 = g_rowptr[warp + 1];

    const float4* qp = (const float4*)(q + (size_t)warp * D1 + lane * 8);
    float4 qa = qp[0], qb = qp[1];
    float accsum = 0.f;
    for (int s = s0; s < s1; s++) {
        int src = g_csrsrc[s];
        const float4* kp = (const float4*)(k + (size_t)src * D1 + lane * 8);
        float4 ka = kp[0], kb = kp[1];
        float p = qa.x * ka.x + qa.y * ka.y + qa.z * ka.z + qa.w * ka.w
                + qb.x * kb.x + qb.y * kb.y + qb.z * kb.z + qb.w * kb.w;
        p += __shfl_xor_sync(0xffffffffu, p, 1);
        p += __shfl_xor_sync(0xffffffffu, p, 2);
        if ((lane & 3) == 0) {
            float e = expf(p * 0.17677669529663687f);  // 1/sqrt(32)
            g_ea1[(size_t)s * H1 + (lane >> 2)] = e;
            accsum += e;
        }
    }
    if ((lane & 3) == 0) g_asum1[warp * H1 + (lane >> 2)] = accsum;
}

__global__ void __launch_bounds__(256) k_aggr1(const float* __restrict__ v, int n)
{
    int warp = (blockIdx.x * blockDim.x + threadIdx.x) >> 5;
    int lane = threadIdx.x & 31;
    if (warp >= n) return;
    int s0 = g_rowptr[warp], s1 = g_rowptr[warp + 1];
    int h = lane >> 2;

    float4 a0 = make_float4(0.f, 0.f, 0.f, 0.f);
    float4 a1 = make_float4(0.f, 0.f, 0.f, 0.f);
    for (int s = s0; s < s1; s++) {
        int src = g_csrsrc[s];
        float e = g_ea1[(size_t)s * H1 + h];
        const float4* vp = (const float4*)(v + (size_t)src * D1 + lane * 8);
        float4 v0 = vp[0], v1 = vp[1];
        a0.x = fmaf(e, v0.x, a0.x); a0.y = fmaf(e, v0.y, a0.y);
        a0.z = fmaf(e, v0.z, a0.z); a0.w = fmaf(e, v0.w, a0.w);
        a1.x = fmaf(e, v1.x, a1.x); a1.y = fmaf(e, v1.y, a1.y);
        a1.z = fmaf(e, v1.z, a1.z); a1.w = fmaf(e, v1.w, a1.w);
    }
    float inv = (s1 > s0) ? 1.0f / g_asum1[warp * H1 + h] : 0.f;
    a0.x *= inv; a0.y *= inv; a0.z *= inv; a0.w *= inv;
    a1.x *= inv; a1.y *= inv; a1.z *= inv; a1.w *= inv;
    float4* op = (float4*)(g_agg1 + (size_t)warp * D1 + lane * 8);
    op[0] = a0; op[1] = a1;
}

__global__ void __launch_bounds__(256) k_combine1(
    const float* __restrict__ bw, int n)
{
    __shared__ float w[3 * D1];
    for (int i = threadIdx.x; i < 3 * D1; i += blockDim.x) w[i] = bw[i];
    __syncthreads();

    int warp = (blockIdx.x * blockDim.x + threadIdx.x) >> 5;
    int lane = threadIdx.x & 31;
    if (warp >= n) return;

    const float4* op = (const float4*)(g_agg1 + (size_t)warp * D1 + lane * 8);
    const float4* sp = (const float4*)(g_s1 + (size_t)warp * D1 + lane * 8);
    float o[8], sk[8];
    float4 t;
    t = op[0]; o[0] = t.x; o[1] = t.y; o[2] = t.z; o[3] = t.w;
    t = op[1]; o[4] = t.x; o[5] = t.y; o[6] = t.z; o[7] = t.w;
    t = sp[0]; sk[0] = t.x; sk[1] = t.y; sk[2] = t.z; sk[3] = t.w;
    t = sp[1]; sk[4] = t.x; sk[5] = t.y; sk[6] = t.z; sk[7] = t.w;

    float g = 0.f;
    #pragma unroll
    for (int j = 0; j < 8; j++) {
        int c = lane * 8 + j;
        g += o[j] * w[c] + sk[j] * w[D1 + c] + (o[j] - sk[j]) * w[2 * D1 + c];
    }
    #pragma unroll
    for (int off = 16; off >= 1; off >>= 1) g += __shfl_xor_sync(0xffffffffu, g, off);
    float beta = 1.0f / (1.0f + expf(-g));

    float r[8];
    #pragma unroll
    for (int j = 0; j < 8; j++) {
        float vv = beta * sk[j] + (1.0f - beta) * o[j];
        r[j] = (vv > 0.f) ? vv : (expf(vv) - 1.0f);  // ELU
    }
    float4* hp = (float4*)(g_h + (size_t)warp * D1 + lane * 8);
    hp[0] = make_float4(r[0], r[1], r[2], r[3]);
    hp[1] = make_float4(r[4], r[5], r[6], r[7]);
}

// ---------------- layer 2 edge passes (single head, 40 ch) ----------------
__global__ void __launch_bounds__(256) k_attn2(int n)
{
    int warp = (blockIdx.x * blockDim.x + threadIdx.x) >> 5;
    int lane = threadIdx.x & 31;
    if (warp >= n) return;
    int s0 = g_rowptr[warp], s1 = g_rowptr[warp + 1];

    float q0 = 0.f, q1 = 0.f;
    if (lane < 20) {
        float2 qq = *(const float2*)(g_q2 + (size_t)warp * NOUT + lane * 2);
        q0 = qq.x; q1 = qq.y;
    }
    float accsum = 0.f;
    for (int s = s0; s < s1; s++) {
        int src = g_csrsrc[s];
        float p = 0.f;
        if (lane < 20) {
            float2 kk = *(const float2*)(g_k2 + (size_t)src * NOUT + lane * 2);
            p = q0 * kk.x + q1 * kk.y;
        }
        #pragma unroll
        for (int off = 16; off >= 1; off >>= 1) p += __shfl_xor_sync(0xffffffffu, p, off);
        if (lane == 0) {
            float e = expf(p * 0.15811388300841897f);  // 1/sqrt(40)
            g_ea2[s] = e;
            accsum += e;
        }
    }
    if (lane == 0) g_asum2[warp] = accsum;
}

__global__ void __launch_bounds__(256) k_aggr2(int n)
{
    int warp = (blockIdx.x * blockDim.x + threadIdx.x) >> 5;
    int lane = threadIdx.x & 31;
    if (warp >= n) return;
    int s0 = g_rowptr[warp], s1 = g_rowptr[warp + 1];

    float a0 = 0.f, a1 = 0.f;
    for (int s = s0; s < s1; s++) {
        int src = g_csrsrc[s];
        float e = g_ea2[s];
        if (lane < 20) {
            float2 vv = *(const float2*)(g_v2 + (size_t)src * NOUT + lane * 2);
            a0 = fmaf(e, vv.x, a0);
            a1 = fmaf(e, vv.y, a1);
        }
    }
    float inv = (s1 > s0) ? 1.0f / g_asum2[warp] : 0.f;
    if (lane < 20)
        *(float2*)(g_agg2 + (size_t)warp * NOUT + lane * 2) = make_float2(a0 * inv, a1 * inv);
}

__global__ void __launch_bounds__(256) k_combine2(
    const float* __restrict__ bw, float* __restrict__ out, int n)
{
    __shared__ float w[3 * NOUT];
    for (int i = threadIdx.x; i < 3 * NOUT; i += blockDim.x) w[i] = bw[i];
    __syncthreads();

    int warp = (blockIdx.x * blockDim.x + threadIdx.x) >> 5;
    int lane = threadIdx.x & 31;
    if (warp >= n) return;

    float o0 = 0.f, o1 = 0.f, s0 = 0.f, s1 = 0.f;
    float g = 0.f;
    if (lane < 20) {
        float2 oo = *(const float2*)(g_agg2 + (size_t)warp * NOUT + lane * 2);
        float2 ss = *(const float2*)(g_s2 + (size_t)warp * NOUT + lane * 2);
        o0 = oo.x; o1 = oo.y; s0 = ss.x; s1 = ss.y;
        int c = lane * 2;
        g = o0 * w[c] + s0 * w[NOUT + c] + (o0 - s0) * w[2 * NOUT + c]
          + o1 * w[c + 1] + s1 * w[NOUT + c + 1] + (o1 - s1) * w[2 * NOUT + c + 1];
    }
    #pragma unroll
    for (int off = 16; off >= 1; off >>= 1) g += __shfl_xor_sync(0xffffffffu, g, off);
    float beta = 1.0f / (1.0f + expf(-g));
    if (lane < 20) {
        float r0 = beta * s0 + (1.0f - beta) * o0;
        float r1 = beta * s1 + (1.0f - beta) * o1;
        *(float2*)(out + (size_t)warp * NOUT + lane * 2) = make_float2(r0, r1);
    }
}

// ---------------- launch ----------------
extern "C" void kernel_launch(void* const* d_in, const int* in_sizes, int n_in,
                              void* d_out, int out_size)
{
    const float* x = (const float*)d_in[0];
    const void* ei = d_in[1];
    const float* q1w = (const float*)d_in[2];
    const float* q1b = (const float*)d_in[3];
    const float* k1w = (const float*)d_in[4];
    const float* k1b = (const float*)d_in[5];
    const float* v1w = (const float*)d_in[6];
    const float* v1b = (const float*)d_in[7];
    const float* s1w = (const float*)d_in[8];
    const float* s1b = (const float*)d_in[9];
    const float* b1w = (const float*)d_in[10];
    const float* q2w = (const float*)d_in[11];
    const float* q2b = (const float*)d_in[12];
    const float* k2w = (const float*)d_in[13];
    const float* k2b = (const float*)d_in[14];
    const float* v2w = (const float*)d_in[15];
    const float* v2b = (const float*)d_in[16];
    const float* s2w = (const float*)d_in[17];
    const float* s2b = (const float*)d_in[18];
    const float* b2w = (const float*)d_in[19];
    float* out = (float*)d_out;

    const int n = in_sizes[0] / FIN;   // 50000
    const int e = in_sizes[1] / 2;     // 800000

    float* d_q1; cudaGetSymbolAddress((void**)&d_q1, g_q1);
    float* d_k1; cudaGetSymbolAddress((void**)&d_k1, g_k1);
    float* d_v1; cudaGetSymbolAddress((void**)&d_v1, g_v1);
    float* d_s1; cudaGetSymbolAddress((void**)&d_s1, g_s1);
    float* d_h;  cudaGetSymbolAddress((void**)&d_h,  g_h);
    float* d_q2; cudaGetSymbolAddress((void**)&d_q2, g_q2);
    float* d_k2; cudaGetSymbolAddress((void**)&d_k2, g_k2);
    float* d_v2; cudaGetSymbolAddress((void**)&d_v2, g_v2);
    float* d_s2; cudaGetSymbolAddress((void**)&d_s2, g_s2);

    // ---- edge dtype detect + convert ----
    k_flag_zero<<<1, 1>>>();
    k_detect<<<cdiv(e, 256), 256>>>((const int*)ei, e);
    k_convert<<<cdiv(e, 256), 256>>>(ei, e);

    // ---- CSR build ----
    k_zero_deg<<<cdiv(n, 256), 256>>>(n);
    k_hist<<<cdiv(e, 256), 256>>>(e);
    k_scan<<<1, 1024>>>(n);
    k_copy_wp<<<cdiv(n, 256), 256>>>(n);
    k_scatter<<<cdiv(e, 256), 256>>>(e);

    // ---- layer 1 projections ----
    {
        dim3 grid(cdiv(n, 128), cdiv(D1, 128));
        k_gemm_bias<128, 128, 16, 8, 8><<<grid, 256>>>(x, q1w, q1b, d_q1, n, FIN, D1);
        k_gemm_bias<128, 128, 16, 8, 8><<<grid, 256>>>(x, k1w, k1b, d_k1, n, FIN, D1);
        k_gemm_bias<128, 128, 16, 8, 8><<<grid, 256>>>(x, v1w, v1b, d_v1, n, FIN, D1);
        k_gemm_bias<128, 128, 16, 8, 8><<<grid, 256>>>(x, s1w, s1b, d_s1, n, FIN, D1);
    }

    int nodeBlocks = cdiv(n * 32, 256);
    k_attn1<<<nodeBlocks, 256>>>(d_q1, d_k1, n);
    k_aggr1<<<nodeBlocks, 256>>>(d_v1, n);
    k_combine1<<<nodeBlocks, 256>>>(b1w, n);

    // ---- layer 2 projections ----
    {
        dim3 grid(cdiv(n, 64), cdiv(NOUT, 64));
        k_gemm_bias<64, 64, 16, 4, 4><<<grid, 256>>>(d_h, q2w, q2b, d_q2, n, D1, NOUT);
        k_gemm_bias<64, 64, 16, 4, 4><<<grid, 256>>>(d_h, k2w, k2b, d_k2, n, D1, NOUT);
        k_gemm_bias<64, 64, 16, 4, 4><<<grid, 256>>>(d_h, v2w, v2b, d_v2, n, D1, NOUT);
        k_gemm_bias<64, 64, 16, 4, 4><<<grid, 256>>>(d_h, s2w, s2b, d_s2, n, D1, NOUT);
    }

    k_attn2<<<nodeBlocks, 256>>>(n);
    k_aggr2<<<nodeBlocks, 256>>>(n);
    k_combine2<<<nodeBlocks, 256>>>(b2w, out, n);
}

// round 6
// speedup vs baseline: 1.4946x; 1.4946x over previous
#include <cuda_runtime.h>
#include <cuda_bf16.h>
#include <math.h>
#include <stdint.h>

// Problem constants
#define NN   50000
#define EE   800000
#define FIN  128
#define D1   256
#define NOUT 40
#define NTOT1 1024   // packed q|k|v|s layer 1 (4*256)
#define NTOT2 160    // packed q|k|v|s layer 2 (4*40)
#define N2P  256     // padded layer-2 N for GEMM tiles

// ---------------- static scratch ----------------
__device__ __align__(256) float g_p1[(size_t)NN * NTOT1];  // packed q1|k1|v1|s1
__device__ __align__(256) float g_p2[(size_t)NN * NTOT2];  // packed q2|k2|v2|s2

__device__ __align__(256) __nv_bfloat16 g_xhi[(size_t)NN * FIN];
__device__ __align__(256) __nv_bfloat16 g_xlo[(size_t)NN * FIN];
__device__ __align__(256) __nv_bfloat16 g_hhi[(size_t)NN * D1];
__device__ __align__(256) __nv_bfloat16 g_hlo[(size_t)NN * D1];
__device__ __align__(256) __nv_bfloat16 g_w1hi[NTOT1 * FIN];  // [n][k] transposed
__device__ __align__(256) __nv_bfloat16 g_w1lo[NTOT1 * FIN];
__device__ __align__(256) __nv_bfloat16 g_w2hi[N2P * D1];     // [n][k], rows >=160 zero
__device__ __align__(256) __nv_bfloat16 g_w2lo[N2P * D1];
__device__ __align__(256) float g_b1[NTOT1];
__device__ __align__(256) float g_b2[N2P];

__device__ __align__(256) int g_esrc[EE];
__device__ __align__(256) int g_edst[EE];
__device__ int g_is32;
__device__ int g_deg[NN];
__device__ __align__(256) int g_rowptr[NN + 1];
__device__ int g_wp[NN];
__device__ __align__(256) int g_csrsrc[EE];

static inline int cdiv(int a, int b) { return (a + b - 1) / b; }

// ---------------- edge dtype detect + convert ----------------
__global__ void k_init(int n) {
    int i = blockIdx.x * blockDim.x + threadIdx.x;
    if (i == 0) g_is32 = 0;
    if (i < n) g_deg[i] = 0;
}
__global__ void k_detect(const int* __restrict__ w, int e) {
    int i = blockIdx.x * blockDim.x + threadIdx.x;
    if (i < e) { if (w[2 * i + 1] != 0) g_is32 = 1; }
}
__global__ void k_convert(const void* __restrict__ ei, int e) {
    int i = blockIdx.x * blockDim.x + threadIdx.x;
    if (i >= e) return;
    if (g_is32) {
        const int* p = (const int*)ei;
        g_esrc[i] = p[i];
        g_edst[i] = p[e + i];
    } else {
        const long long* p = (const long long*)ei;
        g_esrc[i] = (int)p[i];
        g_edst[i] = (int)p[e + i];
    }
}

// ---------------- CSR build ----------------
__global__ void k_hist(int e) {
    int i = blockIdx.x * blockDim.x + threadIdx.x;
    if (i < e) atomicAdd(&g_deg[g_edst[i]], 1);
}
__global__ void k_scan(int n) {
    __shared__ int sh[1024];
    int tid = threadIdx.x;
    int carry = 0;
    for (int base = 0; base <= n; base += 1024) {
        int idx = base + tid;
        int v = (idx < n) ? g_deg[idx] : 0;
        sh[tid] = v;
        __syncthreads();
        #pragma unroll
        for (int off = 1; off < 1024; off <<= 1) {
            int t = (tid >= off) ? sh[tid - off] : 0;
            __syncthreads();
            sh[tid] += t;
            __syncthreads();
        }
        int excl = carry + sh[tid] - v;
        if (idx <= n) {
            g_rowptr[idx] = excl;
            if (idx < n) g_wp[idx] = excl;
        }
        carry += sh[1023];
        __syncthreads();
    }
}
__global__ void k_scatter(int e) {
    int i = blockIdx.x * blockDim.x + threadIdx.x;
    if (i < e) {
        int pos = atomicAdd(&g_wp[g_edst[i]], 1);
        g_csrsrc[pos] = g_esrc[i];
    }
}

// ---------------- weight packing: transpose to [n][k] + split into bf16 hi/lo ----------------
__global__ void k_packw(
    const float* q1w, const float* k1w, const float* v1w, const float* s1w,
    const float* q1b, const float* k1b, const float* v1b, const float* s1b,
    const float* q2w, const float* k2w, const float* v2w, const float* s2w,
    const float* q2b, const float* k2b, const float* v2b, const float* s2b)
{
    int i = blockIdx.x * blockDim.x + threadIdx.x;
    const int W1 = NTOT1 * FIN, W2 = N2P * D1;
    if (i < W1) {
        int n = i / FIN, k = i % FIN;
        const float* s = (n < 256) ? q1w : (n < 512) ? k1w : (n < 768) ? v1w : s1w;
        float v = s[k * 256 + (n & 255)];
        __nv_bfloat16 h = __float2bfloat16(v);
        g_w1hi[i] = h;
        g_w1lo[i] = __float2bfloat16(v - __bfloat162float(h));
    } else if (i < W1 + W2) {
        int j = i - W1;
        int n = j / D1, k = j % D1;
        float v = 0.f;
        if (n < NTOT2) {
            const float* s = (n < 40) ? q2w : (n < 80) ? k2w : (n < 120) ? v2w : s2w;
            v = s[k * 40 + (n % 40)];
        }
        __nv_bfloat16 h = __float2bfloat16(v);
        g_w2hi[j] = h;
        g_w2lo[j] = __float2bfloat16(v - __bfloat162float(h));
    } else if (i < W1 + W2 + NTOT1) {
        int c = i - W1 - W2;
        const float* s = (c < 256) ? q1b : (c < 512) ? k1b : (c < 768) ? v1b : s1b;
        g_b1[c] = s[c & 255];
    } else if (i < W1 + W2 + NTOT1 + N2P) {
        int c = i - W1 - W2 - NTOT1;
        float v = 0.f;
        if (c < NTOT2) {
            const float* s = (c < 40) ? q2b : (c < 80) ? k2b : (c < 120) ? v2b : s2b;
            v = s[c % 40];
        }
        g_b2[c] = v;
    }
}

// ---------------- split fp32 -> bf16 hi/lo ----------------
__global__ void k_split(const float* __restrict__ src,
                        __nv_bfloat16* __restrict__ hi,
                        __nv_bfloat16* __restrict__ lo, int total)
{
    int i = blockIdx.x * blockDim.x + threadIdx.x;
    if (i < total) {
        float v = src[i];
        __nv_bfloat16 h = __float2bfloat16(v);
        hi[i] = h;
        lo[i] = __float2bfloat16(v - __bfloat162float(h));
    }
}

// ---------------- mma.sync bf16 split GEMM ----------------
// C[M, Nvalid] = A[M,K] @ B^T[N,K] + bias ; 3-term split-bf16, fp32 accum.
__device__ __forceinline__ void mma16816(float* c, const uint32_t* a, const uint32_t* b) {
    asm volatile(
        "mma.sync.aligned.m16n8k16.row.col.f32.bf16.bf16.f32 "
        "{%0,%1,%2,%3}, {%4,%5,%6,%7}, {%8,%9}, {%0,%1,%2,%3};\n"
        : "+f"(c[0]), "+f"(c[1]), "+f"(c[2]), "+f"(c[3])
        : "r"(a[0]), "r"(a[1]), "r"(a[2]), "r"(a[3]), "r"(b[0]), "r"(b[1]));
}

#define SMSTR 72  // bf16 row stride in smem (64 data + 8 pad)

__global__ void __launch_bounds__(256) k_mma_simt(
    const __nv_bfloat16* __restrict__ Ahi, const __nv_bfloat16* __restrict__ Alo,
    const __nv_bfloat16* __restrict__ Bhi, const __nv_bfloat16* __restrict__ Blo,
    const float* __restrict__ bias, float* __restrict__ C,
    int M, int K, int Nvalid, int ldc)
{
    __shared__ __nv_bfloat16 As[128 * SMSTR];
    __shared__ __nv_bfloat16 Bs[128 * SMSTR];

    const int tid = threadIdx.x, lane = tid & 31, wid = tid >> 5;
    const int wm = wid & 1, wn = wid >> 1;      // warps 2(M) x 4(N), warp tile 64x32
    const int grp = lane >> 2, thr = lane & 3;
    const int m0 = blockIdx.x * 128, n0 = blockIdx.y * 128;

    float c[4][4][4];
    #pragma unroll
    for (int mt = 0; mt < 4; mt++)
        #pragma unroll
        for (int nt = 0; nt < 4; nt++)
            #pragma unroll
            for (int r = 0; r < 4; r++) c[mt][nt][r] = 0.f;

    const __nv_bfloat16* Aterm[3] = { Ahi, Ahi, Alo };
    const __nv_bfloat16* Bterm[3] = { Bhi, Blo, Bhi };

    for (int t = 0; t < 3; t++) {
        const __nv_bfloat16* A = Aterm[t];
        const __nv_bfloat16* B = Bterm[t];
        for (int kk = 0; kk < K; kk += 64) {
            // stage A: 128 rows x 64 k (uint4 = 8 bf16)
            #pragma unroll
            for (int i = 0; i < 4; i++) {
                int q = tid + i * 256;
                int r = q >> 3, s = q & 7;
                int grow = m0 + r;
                uint4 v = make_uint4(0u, 0u, 0u, 0u);
                if (grow < M) v = *(const uint4*)&A[(size_t)grow * K + kk + s * 8];
                *(uint4*)&As[r * SMSTR + s * 8] = v;
            }
            // stage B: 128 n-rows x 64 k (B stored [N][K], padded rows valid)
            #pragma unroll
            for (int i = 0; i < 4; i++) {
                int q = tid + i * 256;
                int r = q >> 3, s = q & 7;
                *(uint4*)&Bs[r * SMSTR + s * 8] =
                    *(const uint4*)&B[(size_t)(n0 + r) * K + kk + s * 8];
            }
            __syncthreads();

            #pragma unroll
            for (int ks = 0; ks < 4; ks++) {
                uint32_t a[4][4], b[4][2];
                #pragma unroll
                for (int mt = 0; mt < 4; mt++) {
                    int rbase = wm * 64 + mt * 16 + grp;
                    #pragma unroll
                    for (int r = 0; r < 4; r++) {
                        int row = rbase + (r & 1) * 8;
                        int kc = ks * 16 + thr * 2 + (r >> 1) * 8;
                        a[mt][r] = *(const uint32_t*)&As[row * SMSTR + kc];
                    }
                }
                #pragma unroll
                for (int nt = 0; nt < 4; nt++) {
                    int n = wn * 32 + nt * 8 + grp;
                    #pragma unroll
                    for (int r = 0; r < 2; r++) {
                        int kc = ks * 16 + thr * 2 + r * 8;
                        b[nt][r] = *(const uint32_t*)&Bs[n * SMSTR + kc];
                    }
                }
                #pragma unroll
                for (int mt = 0; mt < 4; mt++)
                    #pragma unroll
                    for (int nt = 0; nt < 4; nt++)
                        mma16816(c[mt][nt], a[mt], b[nt]);
            }
            __syncthreads();
        }
    }

    // epilogue: direct STG with bias
    #pragma unroll
    for (int mt = 0; mt < 4; mt++) {
        int row = m0 + wm * 64 + mt * 16 + grp;
        #pragma unroll
        for (int nt = 0; nt < 4; nt++) {
            int col = n0 + wn * 32 + nt * 8 + thr * 2;
            if (col >= Nvalid) continue;
            float b0 = bias[col], b1 = bias[col + 1];
            if (row < M)
                *(float2*)&C[(size_t)row * ldc + col] =
                    make_float2(c[mt][nt][0] + b0, c[mt][nt][1] + b1);
            if (row + 8 < M)
                *(float2*)&C[(size_t)(row + 8) * ldc + col] =
                    make_float2(c[mt][nt][2] + b0, c[mt][nt][3] + b1);
        }
    }
}

// ---------------- fused layer-1 edge pass: attn + aggregate + beta + ELU + split h ----------------
__global__ void __launch_bounds__(256) k_edge1(const float* __restrict__ bw, int n)
{
    __shared__ float w[3 * D1];
    for (int i = threadIdx.x; i < 3 * D1; i += blockDim.x) w[i] = bw[i];
    __syncthreads();

    int warp = (blockIdx.x * blockDim.x + threadIdx.x) >> 5;
    int lane = threadIdx.x & 31;
    if (warp >= n) return;
    int s0 = g_rowptr[warp], s1 = g_rowptr[warp + 1];

    const float* prow = g_p1 + (size_t)warp * NTOT1;
    float4 qa = *(const float4*)(prow + lane * 8);
    float4 qb = *(const float4*)(prow + lane * 8 + 4);

    float a0x=0,a0y=0,a0z=0,a0w=0, a1x=0,a1y=0,a1z=0,a1w=0;
    float asum = 0.f;
    for (int s = s0; s < s1; s++) {
        int src = g_csrsrc[s];
        const float* base = g_p1 + (size_t)src * NTOT1;
        float4 ka = *(const float4*)(base + 256 + lane * 8);
        float4 kb = *(const float4*)(base + 256 + lane * 8 + 4);
        float p = qa.x*ka.x + qa.y*ka.y + qa.z*ka.z + qa.w*ka.w
                + qb.x*kb.x + qb.y*kb.y + qb.z*kb.z + qb.w*kb.w;
        p += __shfl_xor_sync(0xffffffffu, p, 1);
        p += __shfl_xor_sync(0xffffffffu, p, 2);
        float e = expf(p * 0.17677669529663687f);  // 1/sqrt(32)
        asum += e;
        float4 v0 = *(const float4*)(base + 512 + lane * 8);
        float4 v1 = *(const float4*)(base + 512 + lane * 8 + 4);
        a0x = fmaf(e, v0.x, a0x); a0y = fmaf(e, v0.y, a0y);
        a0z = fmaf(e, v0.z, a0z); a0w = fmaf(e, v0.w, a0w);
        a1x = fmaf(e, v1.x, a1x); a1y = fmaf(e, v1.y, a1y);
        a1z = fmaf(e, v1.z, a1z); a1w = fmaf(e, v1.w, a1w);
    }
    float inv = (s1 > s0) ? 1.0f / asum : 0.f;
    float o[8] = { a0x*inv, a0y*inv, a0z*inv, a0w*inv, a1x*inv, a1y*inv, a1z*inv, a1w*inv };

    float4 sa = *(const float4*)(prow + 768 + lane * 8);
    float4 sbv = *(const float4*)(prow + 768 + lane * 8 + 4);
    float sk[8] = { sa.x, sa.y, sa.z, sa.w, sbv.x, sbv.y, sbv.z, sbv.w };

    float g = 0.f;
    #pragma unroll
    for (int j = 0; j < 8; j++) {
        int ccol = lane * 8 + j;
        g += o[j] * w[ccol] + sk[j] * w[D1 + ccol] + (o[j] - sk[j]) * w[2 * D1 + ccol];
    }
    #pragma unroll
    for (int off = 16; off >= 1; off >>= 1) g += __shfl_xor_sync(0xffffffffu, g, off);
    float beta = 1.0f / (1.0f + expf(-g));

    __nv_bfloat162 ph[4], pl[4];
    #pragma unroll
    for (int j = 0; j < 4; j++) {
        float v0 = beta * sk[2*j]   + (1.0f - beta) * o[2*j];
        float v1 = beta * sk[2*j+1] + (1.0f - beta) * o[2*j+1];
        v0 = (v0 > 0.f) ? v0 : (expf(v0) - 1.0f);   // ELU
        v1 = (v1 > 0.f) ? v1 : (expf(v1) - 1.0f);
        __nv_bfloat16 h0 = __float2bfloat16(v0), h1 = __float2bfloat16(v1);
        ph[j] = __halves2bfloat162(h0, h1);
        pl[j] = __halves2bfloat162(__float2bfloat16(v0 - __bfloat162float(h0)),
                                   __float2bfloat16(v1 - __bfloat162float(h1)));
    }
    *(uint4*)&g_hhi[(size_t)warp * D1 + lane * 8] = *(uint4*)ph;
    *(uint4*)&g_hlo[(size_t)warp * D1 + lane * 8] = *(uint4*)pl;
}

// ---------------- fused layer-2 edge pass ----------------
__global__ void __launch_bounds__(256) k_edge2(const float* __restrict__ bw,
                                               float* __restrict__ out, int n)
{
    __shared__ float w[3 * NOUT];
    for (int i = threadIdx.x; i < 3 * NOUT; i += blockDim.x) w[i] = bw[i];
    __syncthreads();

    int warp = (blockIdx.x * blockDim.x + threadIdx.x) >> 5;
    int lane = threadIdx.x & 31;
    if (warp >= n) return;
    int s0 = g_rowptr[warp], s1 = g_rowptr[warp + 1];

    const float* prow = g_p2 + (size_t)warp * NTOT2;
    float q0 = 0.f, q1 = 0.f;
    if (lane < 20) {
        float2 qq = *(const float2*)(prow + lane * 2);
        q0 = qq.x; q1 = qq.y;
    }
    float acc0 = 0.f, acc1 = 0.f, asum = 0.f;
    for (int s = s0; s < s1; s++) {
        int src = g_csrsrc[s];
        const float* base = g_p2 + (size_t)src * NTOT2;
        float p = 0.f, v0 = 0.f, v1 = 0.f;
        if (lane < 20) {
            float2 kk = *(const float2*)(base + 40 + lane * 2);
            p = q0 * kk.x + q1 * kk.y;
            float2 vv = *(const float2*)(base + 80 + lane * 2);
            v0 = vv.x; v1 = vv.y;
        }
        #pragma unroll
        for (int off = 16; off >= 1; off >>= 1) p += __shfl_xor_sync(0xffffffffu, p, off);
        float e = expf(p * 0.15811388300841897f);  // 1/sqrt(40)
        asum += e;
        acc0 = fmaf(e, v0, acc0);
        acc1 = fmaf(e, v1, acc1);
    }
    float inv = (s1 > s0) ? 1.0f / asum : 0.f;
    float o0 = acc0 * inv, o1 = acc1 * inv;

    float sk0 = 0.f, sk1 = 0.f, g = 0.f;
    if (lane < 20) {
        float2 ss = *(const float2*)(prow + 120 + lane * 2);
        sk0 = ss.x; sk1 = ss.y;
        int ccol = lane * 2;
        g = o0 * w[ccol]     + sk0 * w[NOUT + ccol]     + (o0 - sk0) * w[2 * NOUT + ccol]
          + o1 * w[ccol + 1] + sk1 * w[NOUT + ccol + 1] + (o1 - sk1) * w[2 * NOUT + ccol + 1];
    }
    #pragma unroll
    for (int off = 16; off >= 1; off >>= 1) g += __shfl_xor_sync(0xffffffffu, g, off);
    float beta = 1.0f / (1.0f + expf(-g));
    if (lane < 20) {
        float r0 = beta * sk0 + (1.0f - beta) * o0;
        float r1 = beta * sk1 + (1.0f - beta) * o1;
        *(float2*)(out + (size_t)warp * NOUT + lane * 2) = make_float2(r0, r1);
    }
}

// ---------------- launch ----------------
extern "C" void kernel_launch(void* const* d_in, const int* in_sizes, int n_in,
                              void* d_out, int out_size)
{
    const float* x = (const float*)d_in[0];
    const void* ei = d_in[1];
    const float* q1w = (const float*)d_in[2];
    const float* q1b = (const float*)d_in[3];
    const float* k1w = (const float*)d_in[4];
    const float* k1b = (const float*)d_in[5];
    const float* v1w = (const float*)d_in[6];
    const float* v1b = (const float*)d_in[7];
    const float* s1w = (const float*)d_in[8];
    const float* s1b = (const float*)d_in[9];
    const float* b1w = (const float*)d_in[10];
    const float* q2w = (const float*)d_in[11];
    const float* q2b = (const float*)d_in[12];
    const float* k2w = (const float*)d_in[13];
    const float* k2b = (const float*)d_in[14];
    const float* v2w = (const float*)d_in[15];
    const float* v2b = (const float*)d_in[16];
    const float* s2w = (const float*)d_in[17];
    const float* s2b = (const float*)d_in[18];
    const float* b2w = (const float*)d_in[19];
    float* out = (float*)d_out;

    const int n = in_sizes[0] / FIN;   // 50000
    const int e = in_sizes[1] / 2;     // 800000

    float* d_p1; cudaGetSymbolAddress((void**)&d_p1, g_p1);
    float* d_p2; cudaGetSymbolAddress((void**)&d_p2, g_p2);
    __nv_bfloat16 *d_xhi, *d_xlo, *d_hhi, *d_hlo, *d_w1hi, *d_w1lo, *d_w2hi, *d_w2lo;
    cudaGetSymbolAddress((void**)&d_xhi, g_xhi);
    cudaGetSymbolAddress((void**)&d_xlo, g_xlo);
    cudaGetSymbolAddress((void**)&d_hhi, g_hhi);
    cudaGetSymbolAddress((void**)&d_hlo, g_hlo);
    cudaGetSymbolAddress((void**)&d_w1hi, g_w1hi);
    cudaGetSymbolAddress((void**)&d_w1lo, g_w1lo);
    cudaGetSymbolAddress((void**)&d_w2hi, g_w2hi);
    cudaGetSymbolAddress((void**)&d_w2lo, g_w2lo);
    float *d_b1, *d_b2;
    cudaGetSymbolAddress((void**)&d_b1, g_b1);
    cudaGetSymbolAddress((void**)&d_b2, g_b2);

    // ---- edge dtype detect + convert + CSR ----
    k_init<<<cdiv(n, 256), 256>>>(n);
    k_detect<<<cdiv(e, 256), 256>>>((const int*)ei, e);
    k_convert<<<cdiv(e, 256), 256>>>(ei, e);
    k_hist<<<cdiv(e, 256), 256>>>(e);
    k_scan<<<1, 1024>>>(n);
    k_scatter<<<cdiv(e, 256), 256>>>(e);

    // ---- weight packing (transpose + split) ----
    const int packTotal = NTOT1 * FIN + N2P * D1 + NTOT1 + N2P;
    k_packw<<<cdiv(packTotal, 256), 256>>>(
        q1w, k1w, v1w, s1w, q1b, k1b, v1b, s1b,
        q2w, k2w, v2w, s2w, q2b, k2b, v2b, s2b);

    // ---- split x ----
    k_split<<<cdiv(n * FIN, 256), 256>>>(x, d_xhi, d_xlo, n * FIN);

    const int mblocks = cdiv(n, 128);
    const int nodeBlocks = cdiv(n * 32, 256);

    // ---- layer 1: mma.sync split-bf16 projections + fused edge pass ----
    k_mma_simt<<<dim3(mblocks, NTOT1 / 128), 256>>>(
        d_xhi, d_xlo, d_w1hi, d_w1lo, d_b1, d_p1, n, FIN, NTOT1, NTOT1);
    k_edge1<<<nodeBlocks, 256>>>(b1w, n);

    // ---- layer 2 ----
    k_mma_simt<<<dim3(mblocks, N2P / 128), 256>>>(
        d_hhi, d_hlo, d_w2hi, d_w2lo, d_b2, d_p2, n, D1, NTOT2, NTOT2);
    k_edge2<<<nodeBlocks, 256>>>(b2w, out, n);
}

// round 7
// speedup vs baseline: 1.9514x; 1.3056x over previous
#include <cuda_runtime.h>
#include <cuda_bf16.h>
#include <math.h>
#include <stdint.h>

// Problem constants
#define NN   50000
#define EE   800000
#define FIN  128
#define D1   256
#define NOUT 40
#define NTOT1 1024   // packed q|k|v|s layer 1 (4*256)
#define NTOT2 160    // packed q|k|v|s layer 2 (4*40)
#define N2P  256     // padded layer-2 N for GEMM tiles

// ---------------- static scratch ----------------
__device__ __align__(256) float g_p1[(size_t)NN * NTOT1];  // packed q1|k1|v1|s1
__device__ __align__(256) float g_p2[(size_t)NN * NTOT2];  // packed q2|k2|v2|s2

__device__ __align__(256) __nv_bfloat16 g_xhi[(size_t)NN * FIN];
__device__ __align__(256) __nv_bfloat16 g_xlo[(size_t)NN * FIN];
__device__ __align__(256) __nv_bfloat16 g_hhi[(size_t)NN * D1];
__device__ __align__(256) __nv_bfloat16 g_hlo[(size_t)NN * D1];
__device__ __align__(256) __nv_bfloat16 g_w1hi[NTOT1 * FIN];  // [n][k] transposed
__device__ __align__(256) __nv_bfloat16 g_w1lo[NTOT1 * FIN];
__device__ __align__(256) __nv_bfloat16 g_w2hi[N2P * D1];     // [n][k], rows >=160 zero
__device__ __align__(256) __nv_bfloat16 g_w2lo[N2P * D1];
__device__ __align__(256) float g_b1[NTOT1];
__device__ __align__(256) float g_b2[N2P];

__device__ __align__(256) int g_esrc[EE];
__device__ __align__(256) int g_edst[EE];
__device__ int g_is32;
__device__ int g_deg[NN];
__device__ __align__(256) int g_rowptr[NN + 1];
__device__ int g_wp[NN];
__device__ __align__(256) int g_csrsrc[EE];

static inline int cdiv(int a, int b) { return (a + b - 1) / b; }

// ---------------- edge dtype detect + convert ----------------
__global__ void k_init(int n) {
    int i = blockIdx.x * blockDim.x + threadIdx.x;
    if (i == 0) g_is32 = 0;
    if (i < n) g_deg[i] = 0;
}
__global__ void k_detect(const int* __restrict__ w, int e) {
    int i = blockIdx.x * blockDim.x + threadIdx.x;
    if (i < e) { if (w[2 * i + 1] != 0) g_is32 = 1; }
}
__global__ void k_convert(const void* __restrict__ ei, int e) {
    int i = blockIdx.x * blockDim.x + threadIdx.x;
    if (i >= e) return;
    if (g_is32) {
        const int* p = (const int*)ei;
        g_esrc[i] = p[i];
        g_edst[i] = p[e + i];
    } else {
        const long long* p = (const long long*)ei;
        g_esrc[i] = (int)p[i];
        g_edst[i] = (int)p[e + i];
    }
}

// ---------------- CSR build ----------------
__global__ void k_hist(int e) {
    int i = blockIdx.x * blockDim.x + threadIdx.x;
    if (i < e) atomicAdd(&g_deg[g_edst[i]], 1);
}
__global__ void k_scan(int n) {
    __shared__ int sh[1024];
    int tid = threadIdx.x;
    int carry = 0;
    for (int base = 0; base <= n; base += 1024) {
        int idx = base + tid;
        int v = (idx < n) ? g_deg[idx] : 0;
        sh[tid] = v;
        __syncthreads();
        #pragma unroll
        for (int off = 1; off < 1024; off <<= 1) {
            int t = (tid >= off) ? sh[tid - off] : 0;
            __syncthreads();
            sh[tid] += t;
            __syncthreads();
        }
        int excl = carry + sh[tid] - v;
        if (idx <= n) {
            g_rowptr[idx] = excl;
            if (idx < n) g_wp[idx] = excl;
        }
        carry += sh[1023];
        __syncthreads();
    }
}
__global__ void k_scatter(int e) {
    int i = blockIdx.x * blockDim.x + threadIdx.x;
    if (i < e) {
        int pos = atomicAdd(&g_wp[g_edst[i]], 1);
        g_csrsrc[pos] = g_esrc[i];
    }
}

// ---------------- weight packing: transpose to [n][k] + split into bf16 hi/lo ----------------
__global__ void k_packw(
    const float* q1w, const float* k1w, const float* v1w, const float* s1w,
    const float* q1b, const float* k1b, const float* v1b, const float* s1b,
    const float* q2w, const float* k2w, const float* v2w, const float* s2w,
    const float* q2b, const float* k2b, const float* v2b, const float* s2b)
{
    int i = blockIdx.x * blockDim.x + threadIdx.x;
    const int W1 = NTOT1 * FIN, W2 = N2P * D1;
    if (i < W1) {
        int n = i / FIN, k = i % FIN;
        const float* s = (n < 256) ? q1w : (n < 512) ? k1w : (n < 768) ? v1w : s1w;
        float v = s[k * 256 + (n & 255)];
        __nv_bfloat16 h = __float2bfloat16(v);
        g_w1hi[i] = h;
        g_w1lo[i] = __float2bfloat16(v - __bfloat162float(h));
    } else if (i < W1 + W2) {
        int j = i - W1;
        int n = j / D1, k = j % D1;
        float v = 0.f;
        if (n < NTOT2) {
            const float* s = (n < 40) ? q2w : (n < 80) ? k2w : (n < 120) ? v2w : s2w;
            v = s[k * 40 + (n % 40)];
        }
        __nv_bfloat16 h = __float2bfloat16(v);
        g_w2hi[j] = h;
        g_w2lo[j] = __float2bfloat16(v - __bfloat162float(h));
    } else if (i < W1 + W2 + NTOT1) {
        int c = i - W1 - W2;
        const float* s = (c < 256) ? q1b : (c < 512) ? k1b : (c < 768) ? v1b : s1b;
        g_b1[c] = s[c & 255];
    } else if (i < W1 + W2 + NTOT1 + N2P) {
        int c = i - W1 - W2 - NTOT1;
        float v = 0.f;
        if (c < NTOT2) {
            const float* s = (c < 40) ? q2b : (c < 80) ? k2b : (c < 120) ? v2b : s2b;
            v = s[c % 40];
        }
        g_b2[c] = v;
    }
}

// ---------------- split fp32 -> bf16 hi/lo ----------------
__global__ void k_split(const float* __restrict__ src,
                        __nv_bfloat16* __restrict__ hi,
                        __nv_bfloat16* __restrict__ lo, int total)
{
    int i = blockIdx.x * blockDim.x + threadIdx.x;
    if (i < total) {
        float v = src[i];
        __nv_bfloat16 h = __float2bfloat16(v);
        hi[i] = h;
        lo[i] = __float2bfloat16(v - __bfloat162float(h));
    }
}

// ---------------- mma.sync bf16 split GEMM (single K pass, ldmatrix) ----------------
__device__ __forceinline__ void mma16816(float* c, const uint32_t* a, const uint32_t* b) {
    asm volatile(
        "mma.sync.aligned.m16n8k16.row.col.f32.bf16.bf16.f32 "
        "{%0,%1,%2,%3}, {%4,%5,%6,%7}, {%8,%9}, {%0,%1,%2,%3};\n"
        : "+f"(c[0]), "+f"(c[1]), "+f"(c[2]), "+f"(c[3])
        : "r"(a[0]), "r"(a[1]), "r"(a[2]), "r"(a[3]), "r"(b[0]), "r"(b[1]));
}
#define LDSM4(r, addr) \
    asm volatile("ldmatrix.sync.aligned.m8n8.x4.shared.b16 {%0,%1,%2,%3}, [%4];" \
        : "=r"((r)[0]), "=r"((r)[1]), "=r"((r)[2]), "=r"((r)[3]) : "r"(addr))

__device__ __forceinline__ uint32_t smem_u32(const void* p) {
    uint32_t a;
    asm("{ .reg .u64 t; cvta.to.shared.u64 t, %1; cvt.u32.u64 %0, t; }" : "=r"(a) : "l"(p));
    return a;
}

#define SMSTR 72     // bf16 row stride (64 data + 8 pad)
#define TILEB (128 * SMSTR)  // elements per tile

// C[M,*] = A[M,K] @ B^T[N,K] + bias ; 3-term split-bf16 in ONE k-pass.
template <int KCHUNKS>
__global__ void __launch_bounds__(256, 2) k_mma2(
    const __nv_bfloat16* __restrict__ Ahi, const __nv_bfloat16* __restrict__ Alo,
    const __nv_bfloat16* __restrict__ Bhi, const __nv_bfloat16* __restrict__ Blo,
    const float* __restrict__ bias, float* __restrict__ C,
    int M, int Nvalid, int ldc)
{
    constexpr int K = KCHUNKS * 64;
    extern __shared__ __nv_bfloat16 smem[];
    __nv_bfloat16* AsH = smem;
    __nv_bfloat16* AsL = smem + TILEB;
    __nv_bfloat16* BsH = smem + 2 * TILEB;
    __nv_bfloat16* BsL = smem + 3 * TILEB;

    const int tid = threadIdx.x, lane = tid & 31, wid = tid >> 5;
    const int wm = wid & 1, wn = wid >> 1;      // warps 2(M) x 4(N); warp tile 64x32
    const int grp = lane >> 2, thr = lane & 3;
    const int sub = lane >> 3, lr = lane & 7;   // ldmatrix addressing
    const int m0 = blockIdx.x * 128, n0 = blockIdx.y * 128;

    const uint32_t sAH = smem_u32(AsH), sAL = smem_u32(AsL);
    const uint32_t sBH = smem_u32(BsH), sBL = smem_u32(BsL);
    // lane-fixed address components
    const int rA = wm * 64 + lr + (sub & 1) * 8;   // + mt*16
    const int kA = (sub >> 1) * 8;                 // + ks*16
    const int rB = wn * 32 + (sub >> 1) * 8 + lr;  // + p*16
    const int kB = (sub & 1) * 8;                  // + ks*16

    float c[4][4][4];
    #pragma unroll
    for (int mt = 0; mt < 4; mt++)
        #pragma unroll
        for (int nt = 0; nt < 4; nt++)
            #pragma unroll
            for (int r = 0; r < 4; r++) c[mt][nt][r] = 0.f;

    for (int kc = 0; kc < KCHUNKS; kc++) {
        const int kk = kc * 64;
        // stage 4 tiles: 128 rows x 64 k each (uint4 = 8 bf16 per store)
        #pragma unroll
        for (int i = 0; i < 4; i++) {
            int q = tid + i * 256;
            int r = q >> 3, s = q & 7;
            int grow = m0 + r;
            uint4 vh = make_uint4(0u, 0u, 0u, 0u), vl = vh;
            if (grow < M) {
                vh = *(const uint4*)&Ahi[(size_t)grow * K + kk + s * 8];
                vl = *(const uint4*)&Alo[(size_t)grow * K + kk + s * 8];
            }
            *(uint4*)&AsH[r * SMSTR + s * 8] = vh;
            *(uint4*)&AsL[r * SMSTR + s * 8] = vl;
            uint4 wh = *(const uint4*)&Bhi[(size_t)(n0 + r) * K + kk + s * 8];
            uint4 wl = *(const uint4*)&Blo[(size_t)(n0 + r) * K + kk + s * 8];
            *(uint4*)&BsH[r * SMSTR + s * 8] = wh;
            *(uint4*)&BsL[r * SMSTR + s * 8] = wl;
        }
        __syncthreads();

        #pragma unroll
        for (int ks = 0; ks < 4; ks++) {
            const int kb = ks * 16;
            uint32_t ah[4][4], bh[2][4], t[2][4], al4[4];
            // A_hi fragments (4 m-tiles)
            #pragma unroll
            for (int mt = 0; mt < 4; mt++)
                LDSM4(ah[mt], sAH + ((rA + mt * 16) * SMSTR + kb + kA) * 2);
            // B_hi fragments (2 ldmatrix.x4 = 4 n-tiles)
            #pragma unroll
            for (int p = 0; p < 2; p++)
                LDSM4(bh[p], sBH + ((rB + p * 16) * SMSTR + kb + kB) * 2);
            // t0: Ahi * Bhi
            #pragma unroll
            for (int mt = 0; mt < 4; mt++)
                #pragma unroll
                for (int p = 0; p < 2; p++) {
                    mma16816(c[mt][2 * p],     ah[mt], &bh[p][0]);
                    mma16816(c[mt][2 * p + 1], ah[mt], &bh[p][2]);
                }
            // t1: Ahi * Blo (reuse ah)
            #pragma unroll
            for (int p = 0; p < 2; p++)
                LDSM4(t[p], sBL + ((rB + p * 16) * SMSTR + kb + kB) * 2);
            #pragma unroll
            for (int mt = 0; mt < 4; mt++)
                #pragma unroll
                for (int p = 0; p < 2; p++) {
                    mma16816(c[mt][2 * p],     ah[mt], &t[p][0]);
                    mma16816(c[mt][2 * p + 1], ah[mt], &t[p][2]);
                }
            // t2: Alo * Bhi (reuse bh, ah regs recycled per-mt)
            #pragma unroll
            for (int mt = 0; mt < 4; mt++) {
                LDSM4(al4, sAL + ((rA + mt * 16) * SMSTR + kb + kA) * 2);
                #pragma unroll
                for (int p = 0; p < 2; p++) {
                    mma16816(c[mt][2 * p],     al4, &bh[p][0]);
                    mma16816(c[mt][2 * p + 1], al4, &bh[p][2]);
                }
            }
        }
        __syncthreads();
    }

    // epilogue: direct STG with bias
    #pragma unroll
    for (int mt = 0; mt < 4; mt++) {
        int row = m0 + wm * 64 + mt * 16 + grp;
        #pragma unroll
        for (int nt = 0; nt < 4; nt++) {
            int col = n0 + wn * 32 + nt * 8 + thr * 2;
            if (col >= Nvalid) continue;
            float b0 = bias[col], b1 = bias[col + 1];
            if (row < M)
                *(float2*)&C[(size_t)row * ldc + col] =
                    make_float2(c[mt][nt][0] + b0, c[mt][nt][1] + b1);
            if (row + 8 < M)
                *(float2*)&C[(size_t)(row + 8) * ldc + col] =
                    make_float2(c[mt][nt][2] + b0, c[mt][nt][3] + b1);
        }
    }
}

// ---------------- fused layer-1 edge pass: attn + aggregate + beta + ELU + split h ----------------
__global__ void __launch_bounds__(256) k_edge1(const float* __restrict__ bw, int n)
{
    __shared__ float w[3 * D1];
    for (int i = threadIdx.x; i < 3 * D1; i += blockDim.x) w[i] = bw[i];
    __syncthreads();

    int warp = (blockIdx.x * blockDim.x + threadIdx.x) >> 5;
    int lane = threadIdx.x & 31;
    if (warp >= n) return;
    int s0 = g_rowptr[warp], s1 = g_rowptr[warp + 1];

    const float* prow = g_p1 + (size_t)warp * NTOT1;
    float4 qa = *(const float4*)(prow + lane * 8);
    float4 qb = *(const float4*)(prow + lane * 8 + 4);

    float a0x=0,a0y=0,a0z=0,a0w=0, a1x=0,a1y=0,a1z=0,a1w=0;
    float asum = 0.f;
    for (int s = s0; s < s1; s++) {
        int src = g_csrsrc[s];
        const float* base = g_p1 + (size_t)src * NTOT1;
        float4 ka = *(const float4*)(base + 256 + lane * 8);
        float4 kb = *(const float4*)(base + 256 + lane * 8 + 4);
        float p = qa.x*ka.x + qa.y*ka.y + qa.z*ka.z + qa.w*ka.w
                + qb.x*kb.x + qb.y*kb.y + qb.z*kb.z + qb.w*kb.w;
        p += __shfl_xor_sync(0xffffffffu, p, 1);
        p += __shfl_xor_sync(0xffffffffu, p, 2);
        float e = expf(p * 0.17677669529663687f);  // 1/sqrt(32)
        asum += e;
        float4 v0 = *(const float4*)(base + 512 + lane * 8);
        float4 v1 = *(const float4*)(base + 512 + lane * 8 + 4);
        a0x = fmaf(e, v0.x, a0x); a0y = fmaf(e, v0.y, a0y);
        a0z = fmaf(e, v0.z, a0z); a0w = fmaf(e, v0.w, a0w);
        a1x = fmaf(e, v1.x, a1x); a1y = fmaf(e, v1.y, a1y);
        a1z = fmaf(e, v1.z, a1z); a1w = fmaf(e, v1.w, a1w);
    }
    float inv = (s1 > s0) ? 1.0f / asum : 0.f;
    float o[8] = { a0x*inv, a0y*inv, a0z*inv, a0w*inv, a1x*inv, a1y*inv, a1z*inv, a1w*inv };

    float4 sa = *(const float4*)(prow + 768 + lane * 8);
    float4 sbv = *(const float4*)(prow + 768 + lane * 8 + 4);
    float sk[8] = { sa.x, sa.y, sa.z, sa.w, sbv.x, sbv.y, sbv.z, sbv.w };

    float g = 0.f;
    #pragma unroll
    for (int j = 0; j < 8; j++) {
        int ccol = lane * 8 + j;
        g += o[j] * w[ccol] + sk[j] * w[D1 + ccol] + (o[j] - sk[j]) * w[2 * D1 + ccol];
    }
    #pragma unroll
    for (int off = 16; off >= 1; off >>= 1) g += __shfl_xor_sync(0xffffffffu, g, off);
    float beta = 1.0f / (1.0f + expf(-g));

    __nv_bfloat162 ph[4], pl[4];
    #pragma unroll
    for (int j = 0; j < 4; j++) {
        float v0 = beta * sk[2*j]   + (1.0f - beta) * o[2*j];
        float v1 = beta * sk[2*j+1] + (1.0f - beta) * o[2*j+1];
        v0 = (v0 > 0.f) ? v0 : (expf(v0) - 1.0f);   // ELU
        v1 = (v1 > 0.f) ? v1 : (expf(v1) - 1.0f);
        __nv_bfloat16 h0 = __float2bfloat16(v0), h1 = __float2bfloat16(v1);
        ph[j] = __halves2bfloat162(h0, h1);
        pl[j] = __halves2bfloat162(__float2bfloat16(v0 - __bfloat162float(h0)),
                                   __float2bfloat16(v1 - __bfloat162float(h1)));
    }
    *(uint4*)&g_hhi[(size_t)warp * D1 + lane * 8] = *(uint4*)ph;
    *(uint4*)&g_hlo[(size_t)warp * D1 + lane * 8] = *(uint4*)pl;
}

// ---------------- fused layer-2 edge pass ----------------
__global__ void __launch_bounds__(256) k_edge2(const float* __restrict__ bw,
                                               float* __restrict__ out, int n)
{
    __shared__ float w[3 * NOUT];
    for (int i = threadIdx.x; i < 3 * NOUT; i += blockDim.x) w[i] = bw[i];
    __syncthreads();

    int warp = (blockIdx.x * blockDim.x + threadIdx.x) >> 5;
    int lane = threadIdx.x & 31;
    if (warp >= n) return;
    int s0 = g_rowptr[warp], s1 = g_rowptr[warp + 1];

    const float* prow = g_p2 + (size_t)warp * NTOT2;
    float q0 = 0.f, q1 = 0.f;
    if (lane < 20) {
        float2 qq = *(const float2*)(prow + lane * 2);
        q0 = qq.x; q1 = qq.y;
    }
    float acc0 = 0.f, acc1 = 0.f, asum = 0.f;
    for (int s = s0; s < s1; s++) {
        int src = g_csrsrc[s];
        const float* base = g_p2 + (size_t)src * NTOT2;
        float p = 0.f, v0 = 0.f, v1 = 0.f;
        if (lane < 20) {
            float2 kk = *(const float2*)(base + 40 + lane * 2);
            p = q0 * kk.x + q1 * kk.y;
            float2 vv = *(const float2*)(base + 80 + lane * 2);
            v0 = vv.x; v1 = vv.y;
        }
        #pragma unroll
        for (int off = 16; off >= 1; off >>= 1) p += __shfl_xor_sync(0xffffffffu, p, off);
        float e = expf(p * 0.15811388300841897f);  // 1/sqrt(40)
        asum += e;
        acc0 = fmaf(e, v0, acc0);
        acc1 = fmaf(e, v1, acc1);
    }
    float inv = (s1 > s0) ? 1.0f / asum : 0.f;
    float o0 = acc0 * inv, o1 = acc1 * inv;

    float sk0 = 0.f, sk1 = 0.f, g = 0.f;
    if (lane < 20) {
        float2 ss = *(const float2*)(prow + 120 + lane * 2);
        sk0 = ss.x; sk1 = ss.y;
        int ccol = lane * 2;
        g = o0 * w[ccol]     + sk0 * w[NOUT + ccol]     + (o0 - sk0) * w[2 * NOUT + ccol]
          + o1 * w[ccol + 1] + sk1 * w[NOUT + ccol + 1] + (o1 - sk1) * w[2 * NOUT + ccol + 1];
    }
    #pragma unroll
    for (int off = 16; off >= 1; off >>= 1) g += __shfl_xor_sync(0xffffffffu, g, off);
    float beta = 1.0f / (1.0f + expf(-g));
    if (lane < 20) {
        float r0 = beta * sk0 + (1.0f - beta) * o0;
        float r1 = beta * sk1 + (1.0f - beta) * o1;
        *(float2*)(out + (size_t)warp * NOUT + lane * 2) = make_float2(r0, r1);
    }
}

// ---------------- launch ----------------
extern "C" void kernel_launch(void* const* d_in, const int* in_sizes, int n_in,
                              void* d_out, int out_size)
{
    const float* x = (const float*)d_in[0];
    const void* ei = d_in[1];
    const float* q1w = (const float*)d_in[2];
    const float* q1b = (const float*)d_in[3];
    const float* k1w = (const float*)d_in[4];
    const float* k1b = (const float*)d_in[5];
    const float* v1w = (const float*)d_in[6];
    const float* v1b = (const float*)d_in[7];
    const float* s1w = (const float*)d_in[8];
    const float* s1b = (const float*)d_in[9];
    const float* b1w = (const float*)d_in[10];
    const float* q2w = (const float*)d_in[11];
    const float* q2b = (const float*)d_in[12];
    const float* k2w = (const float*)d_in[13];
    const float* k2b = (const float*)d_in[14];
    const float* v2w = (const float*)d_in[15];
    const float* v2b = (const float*)d_in[16];
    const float* s2w = (const float*)d_in[17];
    const float* s2b = (const float*)d_in[18];
    const float* b2w = (const float*)d_in[19];
    float* out = (float*)d_out;

    const int n = in_sizes[0] / FIN;   // 50000
    const int e = in_sizes[1] / 2;     // 800000

    float* d_p1; cudaGetSymbolAddress((void**)&d_p1, g_p1);
    float* d_p2; cudaGetSymbolAddress((void**)&d_p2, g_p2);
    __nv_bfloat16 *d_xhi, *d_xlo, *d_hhi, *d_hlo, *d_w1hi, *d_w1lo, *d_w2hi, *d_w2lo;
    cudaGetSymbolAddress((void**)&d_xhi, g_xhi);
    cudaGetSymbolAddress((void**)&d_xlo, g_xlo);
    cudaGetSymbolAddress((void**)&d_hhi, g_hhi);
    cudaGetSymbolAddress((void**)&d_hlo, g_hlo);
    cudaGetSymbolAddress((void**)&d_w1hi, g_w1hi);
    cudaGetSymbolAddress((void**)&d_w1lo, g_w1lo);
    cudaGetSymbolAddress((void**)&d_w2hi, g_w2hi);
    cudaGetSymbolAddress((void**)&d_w2lo, g_w2lo);
    float *d_b1, *d_b2;
    cudaGetSymbolAddress((void**)&d_b1, g_b1);
    cudaGetSymbolAddress((void**)&d_b2, g_b2);

    const int GSMEM = 4 * TILEB * 2;  // 73728 B
    cudaFuncSetAttribute(k_mma2<2>, cudaFuncAttributeMaxDynamicSharedMemorySize, GSMEM);
    cudaFuncSetAttribute(k_mma2<4>, cudaFuncAttributeMaxDynamicSharedMemorySize, GSMEM);

    const int mblocks = cdiv(n, 128);
    const int nodeBlocks = cdiv(n * 32, 256);

    // launches 1-5: edge convert + packing + split (gemm1 lands at launch #6 for ncu -s 5)
    k_init<<<cdiv(n, 256), 256>>>(n);
    k_detect<<<cdiv(e, 256), 256>>>((const int*)ei, e);
    k_convert<<<cdiv(e, 256), 256>>>(ei, e);
    const int packTotal = NTOT1 * FIN + N2P * D1 + NTOT1 + N2P;
    k_packw<<<cdiv(packTotal, 256), 256>>>(
        q1w, k1w, v1w, s1w, q1b, k1b, v1b, s1b,
        q2w, k2w, v2w, s2w, q2b, k2b, v2b, s2b);
    k_split<<<cdiv(n * FIN, 256), 256>>>(x, d_xhi, d_xlo, n * FIN);

    // ---- layer 1 projections (launch #6) ----
    k_mma2<2><<<dim3(mblocks, NTOT1 / 128), 256, GSMEM>>>(
        d_xhi, d_xlo, d_w1hi, d_w1lo, d_b1, d_p1, n, NTOT1, NTOT1);

    // ---- CSR build (independent of projections) ----
    k_hist<<<cdiv(e, 256), 256>>>(e);
    k_scan<<<1, 1024>>>(n);
    k_scatter<<<cdiv(e, 256), 256>>>(e);

    // ---- layer 1 fused edge pass ----
    k_edge1<<<nodeBlocks, 256>>>(b1w, n);

    // ---- layer 2 ----
    k_mma2<4><<<dim3(mblocks, N2P / 128), 256, GSMEM>>>(
        d_hhi, d_hlo, d_w2hi, d_w2lo, d_b2, d_p2, n, NTOT2, NTOT2);
    k_edge2<<<nodeBlocks, 256>>>(b2w, out, n);
}

// round 8
// speedup vs baseline: 2.1318x; 1.0924x over previous
#include <cuda_runtime.h>
#include <cuda_bf16.h>
#include <math.h>
#include <stdint.h>

// Problem constants
#define NN   50000
#define EE   800000
#define FIN  128
#define D1   256
#define NOUT 40
#define NTOT1 1024   // packed q|k|v|s layer 1 (4*256)
#define NTOT2 160    // packed q|k|v|s layer 2 (4*40)
#define N2P  256     // padded layer-2 N for GEMM tiles

// ---------------- static scratch ----------------
__device__ __align__(256) float g_p1[(size_t)NN * NTOT1];  // packed q1|k1|v1|s1
__device__ __align__(256) float g_p2[(size_t)NN * NTOT2];  // packed q2|k2|v2|s2

__device__ __align__(256) __nv_bfloat16 g_hhi[(size_t)NN * D1];
__device__ __align__(256) __nv_bfloat16 g_hlo[(size_t)NN * D1];
__device__ __align__(256) __nv_bfloat16 g_w1hi[NTOT1 * FIN];  // [n][k] transposed
__device__ __align__(256) __nv_bfloat16 g_w1lo[NTOT1 * FIN];
__device__ __align__(256) __nv_bfloat16 g_w2hi[N2P * D1];     // [n][k], rows >=160 zero
__device__ __align__(256) __nv_bfloat16 g_w2lo[N2P * D1];
__device__ __align__(256) float g_b1[NTOT1];
__device__ __align__(256) float g_b2[N2P];

__device__ __align__(256) int g_esrc[EE];
__device__ __align__(256) int g_edst[EE];
__device__ int g_is32;
__device__ int g_deg[NN];
__device__ __align__(256) int g_rowptr[NN + 1];
__device__ int g_wp[NN];
__device__ __align__(256) int g_csrsrc[EE];

static inline int cdiv(int a, int b) { return (a + b - 1) / b; }

// ---------------- init + edge dtype detect ----------------
__global__ void k_init(int n) {
    int i = blockIdx.x * blockDim.x + threadIdx.x;
    if (i == 0) g_is32 = 0;
    if (i < n) g_deg[i] = 0;
}
__global__ void k_detect(const int* __restrict__ w, int e) {
    int i = blockIdx.x * blockDim.x + threadIdx.x;
    if (i < e) { if (w[2 * i + 1] != 0) g_is32 = 1; }
}
// fused convert + degree histogram
__global__ void k_convhist(const void* __restrict__ ei, int e) {
    int i = blockIdx.x * blockDim.x + threadIdx.x;
    if (i >= e) return;
    int s_, d_;
    if (g_is32) {
        const int* p = (const int*)ei;
        s_ = p[i]; d_ = p[e + i];
    } else {
        const long long* p = (const long long*)ei;
        s_ = (int)p[i]; d_ = (int)p[e + i];
    }
    g_esrc[i] = s_;
    g_edst[i] = d_;
    atomicAdd(&g_deg[d_], 1);
}

// ---------------- CSR: warp-shfl scan + scatter ----------------
__global__ void k_scan(int n) {   // single block, 1024 threads
    __shared__ int wsum[32];
    const int tid = threadIdx.x, lane = tid & 31, wid = tid >> 5;
    int carry = 0;
    for (int base = 0; base <= n; base += 1024) {
        int idx = base + tid;
        int v = (idx < n) ? g_deg[idx] : 0;
        int x = v;
        #pragma unroll
        for (int o = 1; o < 32; o <<= 1) {
            int t = __shfl_up_sync(0xffffffffu, x, o);
            if (lane >= o) x += t;
        }
        if (lane == 31) wsum[wid] = x;
        __syncthreads();
        if (wid == 0) {
            int w = wsum[lane];
            #pragma unroll
            for (int o = 1; o < 32; o <<= 1) {
                int t = __shfl_up_sync(0xffffffffu, w, o);
                if (lane >= o) w += t;
            }
            wsum[lane] = w;
        }
        __syncthreads();
        int pre = wid ? wsum[wid - 1] : 0;
        int excl = carry + pre + x - v;
        if (idx <= n) {
            g_rowptr[idx] = excl;
            if (idx < n) g_wp[idx] = excl;
        }
        carry += wsum[31];
        __syncthreads();
    }
}
__global__ void k_scatter(int e) {
    int i = blockIdx.x * blockDim.x + threadIdx.x;
    if (i < e) {
        int pos = atomicAdd(&g_wp[g_edst[i]], 1);
        g_csrsrc[pos] = g_esrc[i];
    }
}

// ---------------- weight packing: transpose to [n][k], split hi/lo, pre-scale q ----------------
__global__ void k_packw(
    const float* q1w, const float* k1w, const float* v1w, const float* s1w,
    const float* q1b, const float* k1b, const float* v1b, const float* s1b,
    const float* q2w, const float* k2w, const float* v2w, const float* s2w,
    const float* q2b, const float* k2b, const float* v2b, const float* s2b)
{
    const float SC1 = 0.17677669529663687f;   // 1/sqrt(32)
    const float SC2 = 0.15811388300841897f;   // 1/sqrt(40)
    int i = blockIdx.x * blockDim.x + threadIdx.x;
    const int W1 = NTOT1 * FIN, W2 = N2P * D1;
    if (i < W1) {
        int n = i / FIN, k = i % FIN;
        const float* s = (n < 256) ? q1w : (n < 512) ? k1w : (n < 768) ? v1w : s1w;
        float v = s[k * 256 + (n & 255)];
        if (n < 256) v *= SC1;
        __nv_bfloat16 h = __float2bfloat16(v);
        g_w1hi[i] = h;
        g_w1lo[i] = __float2bfloat16(v - __bfloat162float(h));
    } else if (i < W1 + W2) {
        int j = i - W1;
        int n = j / D1, k = j % D1;
        float v = 0.f;
        if (n < NTOT2) {
            const float* s = (n < 40) ? q2w : (n < 80) ? k2w : (n < 120) ? v2w : s2w;
            v = s[k * 40 + (n % 40)];
            if (n < 40) v *= SC2;
        }
        __nv_bfloat16 h = __float2bfloat16(v);
        g_w2hi[j] = h;
        g_w2lo[j] = __float2bfloat16(v - __bfloat162float(h));
    } else if (i < W1 + W2 + NTOT1) {
        int c = i - W1 - W2;
        const float* s = (c < 256) ? q1b : (c < 512) ? k1b : (c < 768) ? v1b : s1b;
        float v = s[c & 255];
        if (c < 256) v *= SC1;
        g_b1[c] = v;
    } else if (i < W1 + W2 + NTOT1 + N2P) {
        int c = i - W1 - W2 - NTOT1;
        float v = 0.f;
        if (c < NTOT2) {
            const float* s = (c < 40) ? q2b : (c < 80) ? k2b : (c < 120) ? v2b : s2b;
            v = s[c % 40];
            if (c < 40) v *= SC2;
        }
        g_b2[c] = v;
    }
}

// ---------------- mma.sync bf16 split GEMM (single K pass, ldmatrix) ----------------
__device__ __forceinline__ void mma16816(float* c, const uint32_t* a, const uint32_t* b) {
    asm volatile(
        "mma.sync.aligned.m16n8k16.row.col.f32.bf16.bf16.f32 "
        "{%0,%1,%2,%3}, {%4,%5,%6,%7}, {%8,%9}, {%0,%1,%2,%3};\n"
        : "+f"(c[0]), "+f"(c[1]), "+f"(c[2]), "+f"(c[3])
        : "r"(a[0]), "r"(a[1]), "r"(a[2]), "r"(a[3]), "r"(b[0]), "r"(b[1]));
}
#define LDSM4(r, addr) \
    asm volatile("ldmatrix.sync.aligned.m8n8.x4.shared.b16 {%0,%1,%2,%3}, [%4];" \
        : "=r"((r)[0]), "=r"((r)[1]), "=r"((r)[2]), "=r"((r)[3]) : "r"(addr))

__device__ __forceinline__ uint32_t smem_u32(const void* p) {
    uint32_t a;
    asm("{ .reg .u64 t; cvta.to.shared.u64 t, %1; cvt.u32.u64 %0, t; }" : "=r"(a) : "l"(p));
    return a;
}

#define SMSTR 72     // bf16 row stride (64 data + 8 pad)
#define TILEB (128 * SMSTR)

// C[M,*] = A[M,K] @ B^T[N,K] + bias ; 3-term split-bf16 in ONE k-pass.
// AF32: A is fp32, split into hi/lo during staging (saves the separate split pass).
template <int KCHUNKS, bool AF32>
__global__ void __launch_bounds__(256, 2) k_mma2(
    const void* __restrict__ Ahi_, const void* __restrict__ Alo_,
    const __nv_bfloat16* __restrict__ Bhi, const __nv_bfloat16* __restrict__ Blo,
    const float* __restrict__ bias, float* __restrict__ C,
    int M, int Nvalid, int ldc)
{
    constexpr int K = KCHUNKS * 64;
    extern __shared__ __nv_bfloat16 smem[];
    __nv_bfloat16* AsH = smem;
    __nv_bfloat16* AsL = smem + TILEB;
    __nv_bfloat16* BsH = smem + 2 * TILEB;
    __nv_bfloat16* BsL = smem + 3 * TILEB;

    const int tid = threadIdx.x, lane = tid & 31, wid = tid >> 5;
    const int wm = wid & 1, wn = wid >> 1;      // warps 2(M) x 4(N); warp tile 64x32
    const int grp = lane >> 2, thr = lane & 3;
    const int sub = lane >> 3, lr = lane & 7;
    const int m0 = blockIdx.x * 128, n0 = blockIdx.y * 128;

    const uint32_t sAH = smem_u32(AsH), sAL = smem_u32(AsL);
    const uint32_t sBH = smem_u32(BsH), sBL = smem_u32(BsL);
    const int rA = wm * 64 + lr + (sub & 1) * 8;
    const int kA = (sub >> 1) * 8;
    const int rB = wn * 32 + (sub >> 1) * 8 + lr;
    const int kB = (sub & 1) * 8;

    float c[4][4][4];
    #pragma unroll
    for (int mt = 0; mt < 4; mt++)
        #pragma unroll
        for (int nt = 0; nt < 4; nt++)
            #pragma unroll
            for (int r = 0; r < 4; r++) c[mt][nt][r] = 0.f;

    for (int kc = 0; kc < KCHUNKS; kc++) {
        const int kk = kc * 64;
        #pragma unroll
        for (int i = 0; i < 4; i++) {
            int q = tid + i * 256;
            int r = q >> 3, s = q & 7;
            int grow = m0 + r;
            if (AF32) {
                const float* A32 = (const float*)Ahi_;
                float4 a0 = make_float4(0.f, 0.f, 0.f, 0.f), a1 = a0;
                if (grow < M) {
                    a0 = *(const float4*)&A32[(size_t)grow * K + kk + s * 8];
                    a1 = *(const float4*)&A32[(size_t)grow * K + kk + s * 8 + 4];
                }
                float vv[8] = { a0.x, a0.y, a0.z, a0.w, a1.x, a1.y, a1.z, a1.w };
                __nv_bfloat162 ph[4], pl[4];
                #pragma unroll
                for (int j = 0; j < 4; j++) {
                    __nv_bfloat16 h0 = __float2bfloat16(vv[2*j]);
                    __nv_bfloat16 h1 = __float2bfloat16(vv[2*j+1]);
                    ph[j] = __halves2bfloat162(h0, h1);
                    pl[j] = __halves2bfloat162(
                        __float2bfloat16(vv[2*j]   - __bfloat162float(h0)),
                        __float2bfloat16(vv[2*j+1] - __bfloat162float(h1)));
                }
                *(uint4*)&AsH[r * SMSTR + s * 8] = *(uint4*)ph;
                *(uint4*)&AsL[r * SMSTR + s * 8] = *(uint4*)pl;
            } else {
                const __nv_bfloat16* Ahi = (const __nv_bfloat16*)Ahi_;
                const __nv_bfloat16* Alo = (const __nv_bfloat16*)Alo_;
                uint4 vh = make_uint4(0u, 0u, 0u, 0u), vl = vh;
                if (grow < M) {
                    vh = *(const uint4*)&Ahi[(size_t)grow * K + kk + s * 8];
                    vl = *(const uint4*)&Alo[(size_t)grow * K + kk + s * 8];
                }
                *(uint4*)&AsH[r * SMSTR + s * 8] = vh;
                *(uint4*)&AsL[r * SMSTR + s * 8] = vl;
            }
            uint4 wh = *(const uint4*)&Bhi[(size_t)(n0 + r) * K + kk + s * 8];
            uint4 wl = *(const uint4*)&Blo[(size_t)(n0 + r) * K + kk + s * 8];
            *(uint4*)&BsH[r * SMSTR + s * 8] = wh;
            *(uint4*)&BsL[r * SMSTR + s * 8] = wl;
        }
        __syncthreads();

        #pragma unroll
        for (int ks = 0; ks < 4; ks++) {
            const int kb = ks * 16;
            uint32_t ah[4][4], bh[2][4], t[2][4], al4[4];
            #pragma unroll
            for (int mt = 0; mt < 4; mt++)
                LDSM4(ah[mt], sAH + ((rA + mt * 16) * SMSTR + kb + kA) * 2);
            #pragma unroll
            for (int p = 0; p < 2; p++)
                LDSM4(bh[p], sBH + ((rB + p * 16) * SMSTR + kb + kB) * 2);
            #pragma unroll
            for (int mt = 0; mt < 4; mt++)
                #pragma unroll
                for (int p = 0; p < 2; p++) {
                    mma16816(c[mt][2 * p],     ah[mt], &bh[p][0]);
                    mma16816(c[mt][2 * p + 1], ah[mt], &bh[p][2]);
                }
            #pragma unroll
            for (int p = 0; p < 2; p++)
                LDSM4(t[p], sBL + ((rB + p * 16) * SMSTR + kb + kB) * 2);
            #pragma unroll
            for (int mt = 0; mt < 4; mt++)
                #pragma unroll
                for (int p = 0; p < 2; p++) {
                    mma16816(c[mt][2 * p],     ah[mt], &t[p][0]);
                    mma16816(c[mt][2 * p + 1], ah[mt], &t[p][2]);
                }
            #pragma unroll
            for (int mt = 0; mt < 4; mt++) {
                LDSM4(al4, sAL + ((rA + mt * 16) * SMSTR + kb + kA) * 2);
                #pragma unroll
                for (int p = 0; p < 2; p++) {
                    mma16816(c[mt][2 * p],     al4, &bh[p][0]);
                    mma16816(c[mt][2 * p + 1], al4, &bh[p][2]);
                }
            }
        }
        __syncthreads();
    }

    #pragma unroll
    for (int mt = 0; mt < 4; mt++) {
        int row = m0 + wm * 64 + mt * 16 + grp;
        #pragma unroll
        for (int nt = 0; nt < 4; nt++) {
            int col = n0 + wn * 32 + nt * 8 + thr * 2;
            if (col >= Nvalid) continue;
            float b0 = bias[col], b1 = bias[col + 1];
            if (row < M)
                *(float2*)&C[(size_t)row * ldc + col] =
                    make_float2(c[mt][nt][0] + b0, c[mt][nt][1] + b1);
            if (row + 8 < M)
                *(float2*)&C[(size_t)(row + 8) * ldc + col] =
                    make_float2(c[mt][nt][2] + b0, c[mt][nt][3] + b1);
        }
    }
}

// ---------------- fused layer-1 edge pass ----------------
__global__ void __launch_bounds__(256) k_edge1(const float* __restrict__ bw, int n)
{
    __shared__ float w[3 * D1];
    for (int i = threadIdx.x; i < 3 * D1; i += blockDim.x) w[i] = bw[i];
    __syncthreads();

    int warp = (blockIdx.x * blockDim.x + threadIdx.x) >> 5;
    int lane = threadIdx.x & 31;
    if (warp >= n) return;
    int s0 = g_rowptr[warp], s1 = g_rowptr[warp + 1];

    const float* prow = g_p1 + (size_t)warp * NTOT1;
    float4 qa = *(const float4*)(prow + lane * 8);
    float4 qb = *(const float4*)(prow + lane * 8 + 4);

    float a0x=0,a0y=0,a0z=0,a0w=0, a1x=0,a1y=0,a1z=0,a1w=0;
    float asum = 0.f;
    for (int s = s0; s < s1; s++) {
        int src = g_csrsrc[s];
        const float* base = g_p1 + (size_t)src * NTOT1;
        float4 ka = *(const float4*)(base + 256 + lane * 8);
        float4 kb = *(const float4*)(base + 256 + lane * 8 + 4);
        float p = qa.x*ka.x + qa.y*ka.y + qa.z*ka.z + qa.w*ka.w
                + qb.x*kb.x + qb.y*kb.y + qb.z*kb.z + qb.w*kb.w;
        p += __shfl_xor_sync(0xffffffffu, p, 1);
        p += __shfl_xor_sync(0xffffffffu, p, 2);
        float e = expf(p);     // q pre-scaled by 1/sqrt(32)
        asum += e;
        float4 v0 = *(const float4*)(base + 512 + lane * 8);
        float4 v1 = *(const float4*)(base + 512 + lane * 8 + 4);
        a0x = fmaf(e, v0.x, a0x); a0y = fmaf(e, v0.y, a0y);
        a0z = fmaf(e, v0.z, a0z); a0w = fmaf(e, v0.w, a0w);
        a1x = fmaf(e, v1.x, a1x); a1y = fmaf(e, v1.y, a1y);
        a1z = fmaf(e, v1.z, a1z); a1w = fmaf(e, v1.w, a1w);
    }
    float inv = (s1 > s0) ? 1.0f / asum : 0.f;
    float o[8] = { a0x*inv, a0y*inv, a0z*inv, a0w*inv, a1x*inv, a1y*inv, a1z*inv, a1w*inv };

    float4 sa = *(const float4*)(prow + 768 + lane * 8);
    float4 sbv = *(const float4*)(prow + 768 + lane * 8 + 4);
    float sk[8] = { sa.x, sa.y, sa.z, sa.w, sbv.x, sbv.y, sbv.z, sbv.w };

    float g = 0.f;
    #pragma unroll
    for (int j = 0; j < 8; j++) {
        int ccol = lane * 8 + j;
        g += o[j] * w[ccol] + sk[j] * w[D1 + ccol] + (o[j] - sk[j]) * w[2 * D1 + ccol];
    }
    #pragma unroll
    for (int off = 16; off >= 1; off >>= 1) g += __shfl_xor_sync(0xffffffffu, g, off);
    float beta = 1.0f / (1.0f + expf(-g));

    __nv_bfloat162 ph[4], pl[4];
    #pragma unroll
    for (int j = 0; j < 4; j++) {
        float v0 = beta * sk[2*j]   + (1.0f - beta) * o[2*j];
        float v1 = beta * sk[2*j+1] + (1.0f - beta) * o[2*j+1];
        v0 = (v0 > 0.f) ? v0 : (expf(v0) - 1.0f);   // ELU
        v1 = (v1 > 0.f) ? v1 : (expf(v1) - 1.0f);
        __nv_bfloat16 h0 = __float2bfloat16(v0), h1 = __float2bfloat16(v1);
        ph[j] = __halves2bfloat162(h0, h1);
        pl[j] = __halves2bfloat162(__float2bfloat16(v0 - __bfloat162float(h0)),
                                   __float2bfloat16(v1 - __bfloat162float(h1)));
    }
    *(uint4*)&g_hhi[(size_t)warp * D1 + lane * 8] = *(uint4*)ph;
    *(uint4*)&g_hlo[(size_t)warp * D1 + lane * 8] = *(uint4*)pl;
}

// ---------------- fused layer-2 edge pass ----------------
__global__ void __launch_bounds__(256) k_edge2(const float* __restrict__ bw,
                                               float* __restrict__ out, int n)
{
    __shared__ float w[3 * NOUT];
    for (int i = threadIdx.x; i < 3 * NOUT; i += blockDim.x) w[i] = bw[i];
    __syncthreads();

    int warp = (blockIdx.x * blockDim.x + threadIdx.x) >> 5;
    int lane = threadIdx.x & 31;
    if (warp >= n) return;
    int s0 = g_rowptr[warp], s1 = g_rowptr[warp + 1];

    const float* prow = g_p2 + (size_t)warp * NTOT2;
    float q0 = 0.f, q1 = 0.f;
    if (lane < 20) {
        float2 qq = *(const float2*)(prow + lane * 2);
        q0 = qq.x; q1 = qq.y;
    }
    float acc0 = 0.f, acc1 = 0.f, asum = 0.f;
    for (int s = s0; s < s1; s++) {
        int src = g_csrsrc[s];
        const float* base = g_p2 + (size_t)src * NTOT2;
        float p = 0.f, v0 = 0.f, v1 = 0.f;
        if (lane < 20) {
            float2 kk = *(const float2*)(base + 40 + lane * 2);
            p = q0 * kk.x + q1 * kk.y;
            float2 vv = *(const float2*)(base + 80 + lane * 2);
            v0 = vv.x; v1 = vv.y;
        }
        #pragma unroll
        for (int off = 16; off >= 1; off >>= 1) p += __shfl_xor_sync(0xffffffffu, p, off);
        float e = expf(p);    // q pre-scaled by 1/sqrt(40)
        asum += e;
        acc0 = fmaf(e, v0, acc0);
        acc1 = fmaf(e, v1, acc1);
    }
    float inv = (s1 > s0) ? 1.0f / asum : 0.f;
    float o0 = acc0 * inv, o1 = acc1 * inv;

    float sk0 = 0.f, sk1 = 0.f, g = 0.f;
    if (lane < 20) {
        float2 ss = *(const float2*)(prow + 120 + lane * 2);
        sk0 = ss.x; sk1 = ss.y;
        int ccol = lane * 2;
        g = o0 * w[ccol]     + sk0 * w[NOUT + ccol]     + (o0 - sk0) * w[2 * NOUT + ccol]
          + o1 * w[ccol + 1] + sk1 * w[NOUT + ccol + 1] + (o1 - sk1) * w[2 * NOUT + ccol + 1];
    }
    #pragma unroll
    for (int off = 16; off >= 1; off >>= 1) g += __shfl_xor_sync(0xffffffffu, g, off);
    float beta = 1.0f / (1.0f + expf(-g));
    if (lane < 20) {
        float r0 = beta * sk0 + (1.0f - beta) * o0;
        float r1 = beta * sk1 + (1.0f - beta) * o1;
        *(float2*)(out + (size_t)warp * NOUT + lane * 2) = make_float2(r0, r1);
    }
}

// ---------------- launch ----------------
extern "C" void kernel_launch(void* const* d_in, const int* in_sizes, int n_in,
                              void* d_out, int out_size)
{
    const float* x = (const float*)d_in[0];
    const void* ei = d_in[1];
    const float* q1w = (const float*)d_in[2];
    const float* q1b = (const float*)d_in[3];
    const float* k1w = (const float*)d_in[4];
    const float* k1b = (const float*)d_in[5];
    const float* v1w = (const float*)d_in[6];
    const float* v1b = (const float*)d_in[7];
    const float* s1w = (const float*)d_in[8];
    const float* s1b = (const float*)d_in[9];
    const float* b1w = (const float*)d_in[10];
    const float* q2w = (const float*)d_in[11];
    const float* q2b = (const float*)d_in[12];
    const float* k2w = (const float*)d_in[13];
    const float* k2b = (const float*)d_in[14];
    const float* v2w = (const float*)d_in[15];
    const float* v2b = (const float*)d_in[16];
    const float* s2w = (const float*)d_in[17];
    const float* s2b = (const float*)d_in[18];
    const float* b2w = (const float*)d_in[19];
    float* out = (float*)d_out;

    const int n = in_sizes[0] / FIN;   // 50000
    const int e = in_sizes[1] / 2;     // 800000

    float* d_p1; cudaGetSymbolAddress((void**)&d_p1, g_p1);
    float* d_p2; cudaGetSymbolAddress((void**)&d_p2, g_p2);
    __nv_bfloat16 *d_hhi, *d_hlo, *d_w1hi, *d_w1lo, *d_w2hi, *d_w2lo;
    cudaGetSymbolAddress((void**)&d_hhi, g_hhi);
    cudaGetSymbolAddress((void**)&d_hlo, g_hlo);
    cudaGetSymbolAddress((void**)&d_w1hi, g_w1hi);
    cudaGetSymbolAddress((void**)&d_w1lo, g_w1lo);
    cudaGetSymbolAddress((void**)&d_w2hi, g_w2hi);
    cudaGetSymbolAddress((void**)&d_w2lo, g_w2lo);
    float *d_b1, *d_b2;
    cudaGetSymbolAddress((void**)&d_b1, g_b1);
    cudaGetSymbolAddress((void**)&d_b2, g_b2);

    // side stream + events for CSR || gemm1 overlap (created once, outside capture)
    static cudaStream_t s2 = 0;
    static cudaEvent_t evA = 0, evB = 0;
    if (!s2)  cudaStreamCreateWithFlags(&s2, cudaStreamNonBlocking);
    if (!evA) cudaEventCreateWithFlags(&evA, cudaEventDisableTiming);
    if (!evB) cudaEventCreateWithFlags(&evB, cudaEventDisableTiming);

    const int GSMEM = 4 * TILEB * 2;  // 73728 B
    cudaFuncSetAttribute((const void*)k_mma2<2, true>,  cudaFuncAttributeMaxDynamicSharedMemorySize, GSMEM);
    cudaFuncSetAttribute((const void*)k_mma2<4, false>, cudaFuncAttributeMaxDynamicSharedMemorySize, GSMEM);

    const int mblocks = cdiv(n, 128);
    const int nodeBlocks = cdiv(n * 32, 256);

    // launches 1-3 (stream 0)
    const int packTotal = NTOT1 * FIN + N2P * D1 + NTOT1 + N2P;
    k_packw<<<cdiv(packTotal, 256), 256>>>(
        q1w, k1w, v1w, s1w, q1b, k1b, v1b, s1b,
        q2w, k2w, v2w, s2w, q2b, k2b, v2b, s2b);
    k_init<<<cdiv(n, 256), 256>>>(n);
    k_detect<<<cdiv(e, 256), 256>>>((const int*)ei, e);

    // fork: CSR chain on s2, gemm1 on stream 0 (launch #4 for ncu)
    cudaEventRecord(evA, 0);
    cudaStreamWaitEvent(s2, evA, 0);

    k_mma2<2, true><<<dim3(mblocks, NTOT1 / 128), 256, GSMEM>>>(
        x, nullptr, d_w1hi, d_w1lo, d_b1, d_p1, n, NTOT1, NTOT1);

    k_convhist<<<cdiv(e, 256), 256, 0, s2>>>(ei, e);
    k_scan<<<1, 1024, 0, s2>>>(n);
    k_scatter<<<cdiv(e, 256), 256, 0, s2>>>(e);
    cudaEventRecord(evB, s2);

    // join: edge1 needs gemm1 (stream 0) + CSR (s2)
    cudaStreamWaitEvent(0, evB, 0);
    k_edge1<<<nodeBlocks, 256>>>(b1w, n);

    // ---- layer 2 ----
    k_mma2<4, false><<<dim3(mblocks, N2P / 128), 256, GSMEM>>>(
        d_hhi, d_hlo, d_w2hi, d_w2lo, d_b2, d_p2, n, NTOT2, NTOT2);
    k_edge2<<<nodeBlocks, 256>>>(b2w, out, n);
}

// round 9
// speedup vs baseline: 2.2531x; 1.0569x over previous
#include <cuda_runtime.h>
#include <cuda_bf16.h>
#include <math.h>
#include <stdint.h>

// Problem constants
#define NN   50000
#define EE   800000
#define FIN  128
#define D1   256
#define NOUT 40
#define NTOT1 1024   // packed q|k|v|s layer 1 (4*256)
#define NTOT2 160    // packed q|k|v|s layer 2 (4*40)
#define N2P  256     // padded layer-2 N for GEMM tiles

// ---------------- static scratch ----------------
__device__ __align__(256) float g_p1[(size_t)NN * NTOT1];  // packed q1|k1|v1|s1
__device__ __align__(256) float g_p2[(size_t)NN * NTOT2];  // packed q2|k2|v2|s2

__device__ __align__(256) __nv_bfloat16 g_hhi[(size_t)NN * D1];
__device__ __align__(256) __nv_bfloat16 g_hlo[(size_t)NN * D1];
__device__ __align__(256) __nv_bfloat16 g_w1hi[NTOT1 * FIN];  // [n][k] transposed
__device__ __align__(256) __nv_bfloat16 g_w1lo[NTOT1 * FIN];
__device__ __align__(256) __nv_bfloat16 g_w2hi[N2P * D1];     // [n][k], rows >=160 zero
__device__ __align__(256) __nv_bfloat16 g_w2lo[N2P * D1];
__device__ __align__(256) float g_b1[NTOT1];
__device__ __align__(256) float g_b2[N2P];

__device__ __align__(256) int g_esrc[EE];
__device__ __align__(256) int g_edst[EE];
__device__ int g_is32;
__device__ int g_deg[NN];
__device__ __align__(256) int g_rowptr[NN + 1];
__device__ int g_wp[NN];
__device__ __align__(256) int g_csrsrc[EE];

static inline int cdiv(int a, int b) { return (a + b - 1) / b; }

// ---------------- init + edge dtype detect ----------------
__global__ void k_init(int n) {
    int i = blockIdx.x * blockDim.x + threadIdx.x;
    if (i == 0) g_is32 = 0;
    if (i < n) g_deg[i] = 0;
}
__global__ void k_detect(const int* __restrict__ w, int e) {
    int i = blockIdx.x * blockDim.x + threadIdx.x;
    if (i < e) { if (w[2 * i + 1] != 0) g_is32 = 1; }
}
// fused convert + degree histogram
__global__ void k_convhist(const void* __restrict__ ei, int e) {
    int i = blockIdx.x * blockDim.x + threadIdx.x;
    if (i >= e) return;
    int s_, d_;
    if (g_is32) {
        const int* p = (const int*)ei;
        s_ = p[i]; d_ = p[e + i];
    } else {
        const long long* p = (const long long*)ei;
        s_ = (int)p[i]; d_ = (int)p[e + i];
    }
    g_esrc[i] = s_;
    g_edst[i] = d_;
    atomicAdd(&g_deg[d_], 1);
}

// ---------------- CSR: warp-shfl scan + scatter ----------------
__global__ void k_scan(int n) {   // single block, 1024 threads
    __shared__ int wsum[32];
    const int tid = threadIdx.x, lane = tid & 31, wid = tid >> 5;
    int carry = 0;
    for (int base = 0; base <= n; base += 1024) {
        int idx = base + tid;
        int v = (idx < n) ? g_deg[idx] : 0;
        int x = v;
        #pragma unroll
        for (int o = 1; o < 32; o <<= 1) {
            int t = __shfl_up_sync(0xffffffffu, x, o);
            if (lane >= o) x += t;
        }
        if (lane == 31) wsum[wid] = x;
        __syncthreads();
        if (wid == 0) {
            int w = wsum[lane];
            #pragma unroll
            for (int o = 1; o < 32; o <<= 1) {
                int t = __shfl_up_sync(0xffffffffu, w, o);
                if (lane >= o) w += t;
            }
            wsum[lane] = w;
        }
        __syncthreads();
        int pre = wid ? wsum[wid - 1] : 0;
        int excl = carry + pre + x - v;
        if (idx <= n) {
            g_rowptr[idx] = excl;
            if (idx < n) g_wp[idx] = excl;
        }
        carry += wsum[31];
        __syncthreads();
    }
}
__global__ void k_scatter(int e) {
    int i = blockIdx.x * blockDim.x + threadIdx.x;
    if (i < e) {
        int pos = atomicAdd(&g_wp[g_edst[i]], 1);
        g_csrsrc[pos] = g_esrc[i];
    }
}

// ---------------- weight packing: transpose to [n][k], split hi/lo, pre-scale q ----------------
__global__ void k_packw(
    const float* q1w, const float* k1w, const float* v1w, const float* s1w,
    const float* q1b, const float* k1b, const float* v1b, const float* s1b,
    const float* q2w, const float* k2w, const float* v2w, const float* s2w,
    const float* q2b, const float* k2b, const float* v2b, const float* s2b)
{
    const float SC1 = 0.17677669529663687f;   // 1/sqrt(32)
    const float SC2 = 0.15811388300841897f;   // 1/sqrt(40)
    int i = blockIdx.x * blockDim.x + threadIdx.x;
    const int W1 = NTOT1 * FIN, W2 = N2P * D1;
    if (i < W1) {
        int n = i / FIN, k = i % FIN;
        const float* s = (n < 256) ? q1w : (n < 512) ? k1w : (n < 768) ? v1w : s1w;
        float v = s[k * 256 + (n & 255)];
        if (n < 256) v *= SC1;
        __nv_bfloat16 h = __float2bfloat16(v);
        g_w1hi[i] = h;
        g_w1lo[i] = __float2bfloat16(v - __bfloat162float(h));
    } else if (i < W1 + W2) {
        int j = i - W1;
        int n = j / D1, k = j % D1;
        float v = 0.f;
        if (n < NTOT2) {
            const float* s = (n < 40) ? q2w : (n < 80) ? k2w : (n < 120) ? v2w : s2w;
            v = s[k * 40 + (n % 40)];
            if (n < 40) v *= SC2;
        }
        __nv_bfloat16 h = __float2bfloat16(v);
        g_w2hi[j] = h;
        g_w2lo[j] = __float2bfloat16(v - __bfloat162float(h));
    } else if (i < W1 + W2 + NTOT1) {
        int c = i - W1 - W2;
        const float* s = (c < 256) ? q1b : (c < 512) ? k1b : (c < 768) ? v1b : s1b;
        float v = s[c & 255];
        if (c < 256) v *= SC1;
        g_b1[c] = v;
    } else if (i < W1 + W2 + NTOT1 + N2P) {
        int c = i - W1 - W2 - NTOT1;
        float v = 0.f;
        if (c < NTOT2) {
            const float* s = (c < 40) ? q2b : (c < 80) ? k2b : (c < 120) ? v2b : s2b;
            v = s[c % 40];
            if (c < 40) v *= SC2;
        }
        g_b2[c] = v;
    }
}

// ---------------- mma.sync bf16 split GEMM (single K pass, ldmatrix) ----------------
__device__ __forceinline__ void mma16816(float* c, const uint32_t* a, const uint32_t* b) {
    asm volatile(
        "mma.sync.aligned.m16n8k16.row.col.f32.bf16.bf16.f32 "
        "{%0,%1,%2,%3}, {%4,%5,%6,%7}, {%8,%9}, {%0,%1,%2,%3};\n"
        : "+f"(c[0]), "+f"(c[1]), "+f"(c[2]), "+f"(c[3])
        : "r"(a[0]), "r"(a[1]), "r"(a[2]), "r"(a[3]), "r"(b[0]), "r"(b[1]));
}
#define LDSM4(r, addr) \
    asm volatile("ldmatrix.sync.aligned.m8n8.x4.shared.b16 {%0,%1,%2,%3}, [%4];" \
        : "=r"((r)[0]), "=r"((r)[1]), "=r"((r)[2]), "=r"((r)[3]) : "r"(addr))

__device__ __forceinline__ uint32_t smem_u32(const void* p) {
    uint32_t a;
    asm("{ .reg .u64 t; cvta.to.shared.u64 t, %1; cvt.u32.u64 %0, t; }" : "=r"(a) : "l"(p));
    return a;
}

#define SMSTR 72     // bf16 row stride (64 data + 8 pad)
#define TILEB (128 * SMSTR)

// C[M,*] = A[M,K] @ B^T[N,K] + bias ; 3-term split-bf16 in ONE k-pass.
// Grid: blockIdx.x = n-block (fast) so A tiles stay L2-resident across n-blocks.
// AF32: A is fp32, split into hi/lo during staging.
template <int KCHUNKS, bool AF32>
__global__ void __launch_bounds__(256, 2) k_mma2(
    const void* __restrict__ Ahi_, const void* __restrict__ Alo_,
    const __nv_bfloat16* __restrict__ Bhi, const __nv_bfloat16* __restrict__ Blo,
    const float* __restrict__ bias, float* __restrict__ C,
    int M, int Nvalid, int ldc)
{
    constexpr int K = KCHUNKS * 64;
    extern __shared__ __nv_bfloat16 smem[];
    __nv_bfloat16* AsH = smem;
    __nv_bfloat16* AsL = smem + TILEB;
    __nv_bfloat16* BsH = smem + 2 * TILEB;
    __nv_bfloat16* BsL = smem + 3 * TILEB;

    const int tid = threadIdx.x, lane = tid & 31, wid = tid >> 5;
    const int wm = wid & 1, wn = wid >> 1;      // warps 2(M) x 4(N); warp tile 64x32
    const int grp = lane >> 2, thr = lane & 3;
    const int sub = lane >> 3, lr = lane & 7;
    const int m0 = blockIdx.y * 128, n0 = blockIdx.x * 128;   // SWAPPED: n fast

    const uint32_t sAH = smem_u32(AsH), sAL = smem_u32(AsL);
    const uint32_t sBH = smem_u32(BsH), sBL = smem_u32(BsL);
    const int rA = wm * 64 + lr + (sub & 1) * 8;
    const int kA = (sub >> 1) * 8;
    const int rB = wn * 32 + (sub >> 1) * 8 + lr;
    const int kB = (sub & 1) * 8;

    float c[4][4][4];
    #pragma unroll
    for (int mt = 0; mt < 4; mt++)
        #pragma unroll
        for (int nt = 0; nt < 4; nt++)
            #pragma unroll
            for (int r = 0; r < 4; r++) c[mt][nt][r] = 0.f;

    for (int kc = 0; kc < KCHUNKS; kc++) {
        const int kk = kc * 64;
        #pragma unroll
        for (int i = 0; i < 4; i++) {
            int q = tid + i * 256;
            int r = q >> 3, s = q & 7;
            int grow = m0 + r;
            if (AF32) {
                const float* A32 = (const float*)Ahi_;
                float4 a0 = make_float4(0.f, 0.f, 0.f, 0.f), a1 = a0;
                if (grow < M) {
                    a0 = *(const float4*)&A32[(size_t)grow * K + kk + s * 8];
                    a1 = *(const float4*)&A32[(size_t)grow * K + kk + s * 8 + 4];
                }
                float vv[8] = { a0.x, a0.y, a0.z, a0.w, a1.x, a1.y, a1.z, a1.w };
                __nv_bfloat162 ph[4], pl[4];
                #pragma unroll
                for (int j = 0; j < 4; j++) {
                    __nv_bfloat16 h0 = __float2bfloat16(vv[2*j]);
                    __nv_bfloat16 h1 = __float2bfloat16(vv[2*j+1]);
                    ph[j] = __halves2bfloat162(h0, h1);
                    pl[j] = __halves2bfloat162(
                        __float2bfloat16(vv[2*j]   - __bfloat162float(h0)),
                        __float2bfloat16(vv[2*j+1] - __bfloat162float(h1)));
                }
                *(uint4*)&AsH[r * SMSTR + s * 8] = *(uint4*)ph;
                *(uint4*)&AsL[r * SMSTR + s * 8] = *(uint4*)pl;
            } else {
                const __nv_bfloat16* Ahi = (const __nv_bfloat16*)Ahi_;
                const __nv_bfloat16* Alo = (const __nv_bfloat16*)Alo_;
                uint4 vh = make_uint4(0u, 0u, 0u, 0u), vl = vh;
                if (grow < M) {
                    vh = *(const uint4*)&Ahi[(size_t)grow * K + kk + s * 8];
                    vl = *(const uint4*)&Alo[(size_t)grow * K + kk + s * 8];
                }
                *(uint4*)&AsH[r * SMSTR + s * 8] = vh;
                *(uint4*)&AsL[r * SMSTR + s * 8] = vl;
            }
            uint4 wh = *(const uint4*)&Bhi[(size_t)(n0 + r) * K + kk + s * 8];
            uint4 wl = *(const uint4*)&Blo[(size_t)(n0 + r) * K + kk + s * 8];
            *(uint4*)&BsH[r * SMSTR + s * 8] = wh;
            *(uint4*)&BsL[r * SMSTR + s * 8] = wl;
        }
        __syncthreads();

        #pragma unroll
        for (int ks = 0; ks < 4; ks++) {
            const int kb = ks * 16;
            uint32_t ah[4][4], bh[2][4], t[2][4], al4[4];
            #pragma unroll
            for (int mt = 0; mt < 4; mt++)
                LDSM4(ah[mt], sAH + ((rA + mt * 16) * SMSTR + kb + kA) * 2);
            #pragma unroll
            for (int p = 0; p < 2; p++)
                LDSM4(bh[p], sBH + ((rB + p * 16) * SMSTR + kb + kB) * 2);
            #pragma unroll
            for (int mt = 0; mt < 4; mt++)
                #pragma unroll
                for (int p = 0; p < 2; p++) {
                    mma16816(c[mt][2 * p],     ah[mt], &bh[p][0]);
                    mma16816(c[mt][2 * p + 1], ah[mt], &bh[p][2]);
                }
            #pragma unroll
            for (int p = 0; p < 2; p++)
                LDSM4(t[p], sBL + ((rB + p * 16) * SMSTR + kb + kB) * 2);
            #pragma unroll
            for (int mt = 0; mt < 4; mt++)
                #pragma unroll
                for (int p = 0; p < 2; p++) {
                    mma16816(c[mt][2 * p],     ah[mt], &t[p][0]);
                    mma16816(c[mt][2 * p + 1], ah[mt], &t[p][2]);
                }
            #pragma unroll
            for (int mt = 0; mt < 4; mt++) {
                LDSM4(al4, sAL + ((rA + mt * 16) * SMSTR + kb + kA) * 2);
                #pragma unroll
                for (int p = 0; p < 2; p++) {
                    mma16816(c[mt][2 * p],     al4, &bh[p][0]);
                    mma16816(c[mt][2 * p + 1], al4, &bh[p][2]);
                }
            }
        }
        __syncthreads();
    }

    #pragma unroll
    for (int mt = 0; mt < 4; mt++) {
        int row = m0 + wm * 64 + mt * 16 + grp;
        #pragma unroll
        for (int nt = 0; nt < 4; nt++) {
            int col = n0 + wn * 32 + nt * 8 + thr * 2;
            if (col >= Nvalid) continue;
            float b0 = bias[col], b1 = bias[col + 1];
            if (row < M)
                *(float2*)&C[(size_t)row * ldc + col] =
                    make_float2(c[mt][nt][0] + b0, c[mt][nt][1] + b1);
            if (row + 8 < M)
                *(float2*)&C[(size_t)(row + 8) * ldc + col] =
                    make_float2(c[mt][nt][2] + b0, c[mt][nt][3] + b1);
        }
    }
}

// ---------------- fused layer-1 edge pass (unrolled x2 gather) ----------------
__global__ void __launch_bounds__(256) k_edge1(const float* __restrict__ bw, int n)
{
    __shared__ float w[3 * D1];
    for (int i = threadIdx.x; i < 3 * D1; i += blockDim.x) w[i] = bw[i];
    __syncthreads();

    int warp = (blockIdx.x * blockDim.x + threadIdx.x) >> 5;
    int lane = threadIdx.x & 31;
    if (warp >= n) return;
    int s0 = g_rowptr[warp], s1 = g_rowptr[warp + 1];

    const float* prow = g_p1 + (size_t)warp * NTOT1;
    float4 qa = *(const float4*)(prow + lane * 8);
    float4 qb = *(const float4*)(prow + lane * 8 + 4);

    float a0x=0,a0y=0,a0z=0,a0w=0, a1x=0,a1y=0,a1z=0,a1w=0;
    float asum = 0.f;
    int s = s0;
    for (; s + 1 < s1; s += 2) {
        int src0 = g_csrsrc[s], src1 = g_csrsrc[s + 1];
        const float* b0p = g_p1 + (size_t)src0 * NTOT1;
        const float* b1p = g_p1 + (size_t)src1 * NTOT1;
        // issue all 8 gathers up front (k + v for both edges)
        float4 ka0 = *(const float4*)(b0p + 256 + lane * 8);
        float4 kb0 = *(const float4*)(b0p + 256 + lane * 8 + 4);
        float4 ka1 = *(const float4*)(b1p + 256 + lane * 8);
        float4 kb1 = *(const float4*)(b1p + 256 + lane * 8 + 4);
        float4 v00 = *(const float4*)(b0p + 512 + lane * 8);
        float4 v01 = *(const float4*)(b0p + 512 + lane * 8 + 4);
        float4 v10 = *(const float4*)(b1p + 512 + lane * 8);
        float4 v11 = *(const float4*)(b1p + 512 + lane * 8 + 4);

        float p0 = qa.x*ka0.x + qa.y*ka0.y + qa.z*ka0.z + qa.w*ka0.w
                 + qb.x*kb0.x + qb.y*kb0.y + qb.z*kb0.z + qb.w*kb0.w;
        float p1 = qa.x*ka1.x + qa.y*ka1.y + qa.z*ka1.z + qa.w*ka1.w
                 + qb.x*kb1.x + qb.y*kb1.y + qb.z*kb1.z + qb.w*kb1.w;
        p0 += __shfl_xor_sync(0xffffffffu, p0, 1);
        p0 += __shfl_xor_sync(0xffffffffu, p0, 2);
        p1 += __shfl_xor_sync(0xffffffffu, p1, 1);
        p1 += __shfl_xor_sync(0xffffffffu, p1, 2);
        float e0 = expf(p0), e1 = expf(p1);   // q pre-scaled by 1/sqrt(32)
        asum += e0 + e1;
        a0x = fmaf(e0, v00.x, a0x); a0y = fmaf(e0, v00.y, a0y);
        a0z = fmaf(e0, v00.z, a0z); a0w = fmaf(e0, v00.w, a0w);
        a1x = fmaf(e0, v01.x, a1x); a1y = fmaf(e0, v01.y, a1y);
        a1z = fmaf(e0, v01.z, a1z); a1w = fmaf(e0, v01.w, a1w);
        a0x = fmaf(e1, v10.x, a0x); a0y = fmaf(e1, v10.y, a0y);
        a0z = fmaf(e1, v10.z, a0z); a0w = fmaf(e1, v10.w, a0w);
        a1x = fmaf(e1, v11.x, a1x); a1y = fmaf(e1, v11.y, a1y);
        a1z = fmaf(e1, v11.z, a1z); a1w = fmaf(e1, v11.w, a1w);
    }
    if (s < s1) {
        int src = g_csrsrc[s];
        const float* base = g_p1 + (size_t)src * NTOT1;
        float4 ka = *(const float4*)(base + 256 + lane * 8);
        float4 kb = *(const float4*)(base + 256 + lane * 8 + 4);
        float4 v0 = *(const float4*)(base + 512 + lane * 8);
        float4 v1 = *(const float4*)(base + 512 + lane * 8 + 4);
        float p = qa.x*ka.x + qa.y*ka.y + qa.z*ka.z + qa.w*ka.w
                + qb.x*kb.x + qb.y*kb.y + qb.z*kb.z + qb.w*kb.w;
        p += __shfl_xor_sync(0xffffffffu, p, 1);
        p += __shfl_xor_sync(0xffffffffu, p, 2);
        float e = expf(p);
        asum += e;
        a0x = fmaf(e, v0.x, a0x); a0y = fmaf(e, v0.y, a0y);
        a0z = fmaf(e, v0.z, a0z); a0w = fmaf(e, v0.w, a0w);
        a1x = fmaf(e, v1.x, a1x); a1y = fmaf(e, v1.y, a1y);
        a1z = fmaf(e, v1.z, a1z); a1w = fmaf(e, v1.w, a1w);
    }
    float inv = (s1 > s0) ? 1.0f / asum : 0.f;
    float o[8] = { a0x*inv, a0y*inv, a0z*inv, a0w*inv, a1x*inv, a1y*inv, a1z*inv, a1w*inv };

    float4 sa = *(const float4*)(prow + 768 + lane * 8);
    float4 sbv = *(const float4*)(prow + 768 + lane * 8 + 4);
    float sk[8] = { sa.x, sa.y, sa.z, sa.w, sbv.x, sbv.y, sbv.z, sbv.w };

    float g = 0.f;
    #pragma unroll
    for (int j = 0; j < 8; j++) {
        int ccol = lane * 8 + j;
        g += o[j] * w[ccol] + sk[j] * w[D1 + ccol] + (o[j] - sk[j]) * w[2 * D1 + ccol];
    }
    #pragma unroll
    for (int off = 16; off >= 1; off >>= 1) g += __shfl_xor_sync(0xffffffffu, g, off);
    float beta = 1.0f / (1.0f + expf(-g));

    __nv_bfloat162 ph[4], pl[4];
    #pragma unroll
    for (int j = 0; j < 4; j++) {
        float v0 = beta * sk[2*j]   + (1.0f - beta) * o[2*j];
        float v1 = beta * sk[2*j+1] + (1.0f - beta) * o[2*j+1];
        v0 = (v0 > 0.f) ? v0 : (expf(v0) - 1.0f);   // ELU
        v1 = (v1 > 0.f) ? v1 : (expf(v1) - 1.0f);
        __nv_bfloat16 h0 = __float2bfloat16(v0), h1 = __float2bfloat16(v1);
        ph[j] = __halves2bfloat162(h0, h1);
        pl[j] = __halves2bfloat162(__float2bfloat16(v0 - __bfloat162float(h0)),
                                   __float2bfloat16(v1 - __bfloat162float(h1)));
    }
    *(uint4*)&g_hhi[(size_t)warp * D1 + lane * 8] = *(uint4*)ph;
    *(uint4*)&g_hlo[(size_t)warp * D1 + lane * 8] = *(uint4*)pl;
}

// ---------------- fused layer-2 edge pass ----------------
__global__ void __launch_bounds__(256) k_edge2(const float* __restrict__ bw,
                                               float* __restrict__ out, int n)
{
    __shared__ float w[3 * NOUT];
    for (int i = threadIdx.x; i < 3 * NOUT; i += blockDim.x) w[i] = bw[i];
    __syncthreads();

    int warp = (blockIdx.x * blockDim.x + threadIdx.x) >> 5;
    int lane = threadIdx.x & 31;
    if (warp >= n) return;
    int s0 = g_rowptr[warp], s1 = g_rowptr[warp + 1];

    const float* prow = g_p2 + (size_t)warp * NTOT2;
    float q0 = 0.f, q1 = 0.f;
    if (lane < 20) {
        float2 qq = *(const float2*)(prow + lane * 2);
        q0 = qq.x; q1 = qq.y;
    }
    float acc0 = 0.f, acc1 = 0.f, asum = 0.f;
    for (int s = s0; s < s1; s++) {
        int src = g_csrsrc[s];
        const float* base = g_p2 + (size_t)src * NTOT2;
        float p = 0.f, v0 = 0.f, v1 = 0.f;
        if (lane < 20) {
            float2 kk = *(const float2*)(base + 40 + lane * 2);
            p = q0 * kk.x + q1 * kk.y;
            float2 vv = *(const float2*)(base + 80 + lane * 2);
            v0 = vv.x; v1 = vv.y;
        }
        #pragma unroll
        for (int off = 16; off >= 1; off >>= 1) p += __shfl_xor_sync(0xffffffffu, p, off);
        float e = expf(p);    // q pre-scaled by 1/sqrt(40)
        asum += e;
        acc0 = fmaf(e, v0, acc0);
        acc1 = fmaf(e, v1, acc1);
    }
    float inv = (s1 > s0) ? 1.0f / asum : 0.f;
    float o0 = acc0 * inv, o1 = acc1 * inv;

    float sk0 = 0.f, sk1 = 0.f, g = 0.f;
    if (lane < 20) {
        float2 ss = *(const float2*)(prow + 120 + lane * 2);
        sk0 = ss.x; sk1 = ss.y;
        int ccol = lane * 2;
        g = o0 * w[ccol]     + sk0 * w[NOUT + ccol]     + (o0 - sk0) * w[2 * NOUT + ccol]
          + o1 * w[ccol + 1] + sk1 * w[NOUT + ccol + 1] + (o1 - sk1) * w[2 * NOUT + ccol + 1];
    }
    #pragma unroll
    for (int off = 16; off >= 1; off >>= 1) g += __shfl_xor_sync(0xffffffffu, g, off);
    float beta = 1.0f / (1.0f + expf(-g));
    if (lane < 20) {
        float r0 = beta * sk0 + (1.0f - beta) * o0;
        float r1 = beta * sk1 + (1.0f - beta) * o1;
        *(float2*)(out + (size_t)warp * NOUT + lane * 2) = make_float2(r0, r1);
    }
}

// ---------------- launch ----------------
extern "C" void kernel_launch(void* const* d_in, const int* in_sizes, int n_in,
                              void* d_out, int out_size)
{
    const float* x = (const float*)d_in[0];
    const void* ei = d_in[1];
    const float* q1w = (const float*)d_in[2];
    const float* q1b = (const float*)d_in[3];
    const float* k1w = (const float*)d_in[4];
    const float* k1b = (const float*)d_in[5];
    const float* v1w = (const float*)d_in[6];
    const float* v1b = (const float*)d_in[7];
    const float* s1w = (const float*)d_in[8];
    const float* s1b = (const float*)d_in[9];
    const float* b1w = (const float*)d_in[10];
    const float* q2w = (const float*)d_in[11];
    const float* q2b = (const float*)d_in[12];
    const float* k2w = (const float*)d_in[13];
    const float* k2b = (const float*)d_in[14];
    const float* v2w = (const float*)d_in[15];
    const float* v2b = (const float*)d_in[16];
    const float* s2w = (const float*)d_in[17];
    const float* s2b = (const float*)d_in[18];
    const float* b2w = (const float*)d_in[19];
    float* out = (float*)d_out;

    const int n = in_sizes[0] / FIN;   // 50000
    const int e = in_sizes[1] / 2;     // 800000

    float* d_p1; cudaGetSymbolAddress((void**)&d_p1, g_p1);
    float* d_p2; cudaGetSymbolAddress((void**)&d_p2, g_p2);
    __nv_bfloat16 *d_hhi, *d_hlo, *d_w1hi, *d_w1lo, *d_w2hi, *d_w2lo;
    cudaGetSymbolAddress((void**)&d_hhi, g_hhi);
    cudaGetSymbolAddress((void**)&d_hlo, g_hlo);
    cudaGetSymbolAddress((void**)&d_w1hi, g_w1hi);
    cudaGetSymbolAddress((void**)&d_w1lo, g_w1lo);
    cudaGetSymbolAddress((void**)&d_w2hi, g_w2hi);
    cudaGetSymbolAddress((void**)&d_w2lo, g_w2lo);
    float *d_b1, *d_b2;
    cudaGetSymbolAddress((void**)&d_b1, g_b1);
    cudaGetSymbolAddress((void**)&d_b2, g_b2);

    // side stream + events for CSR || gemm1 overlap (created once, outside capture)
    static cudaStream_t s2 = 0;
    static cudaEvent_t evA = 0, evB = 0;
    if (!s2)  cudaStreamCreateWithFlags(&s2, cudaStreamNonBlocking);
    if (!evA) cudaEventCreateWithFlags(&evA, cudaEventDisableTiming);
    if (!evB) cudaEventCreateWithFlags(&evB, cudaEventDisableTiming);

    const int GSMEM = 4 * TILEB * 2;  // 73728 B
    cudaFuncSetAttribute((const void*)k_mma2<2, true>,  cudaFuncAttributeMaxDynamicSharedMemorySize, GSMEM);
    cudaFuncSetAttribute((const void*)k_mma2<4, false>, cudaFuncAttributeMaxDynamicSharedMemorySize, GSMEM);

    const int mblocks = cdiv(n, 128);
    const int nodeBlocks = cdiv(n * 32, 256);

    // launches 1-3 (stream 0)
    const int packTotal = NTOT1 * FIN + N2P * D1 + NTOT1 + N2P;
    k_packw<<<cdiv(packTotal, 256), 256>>>(
        q1w, k1w, v1w, s1w, q1b, k1b, v1b, s1b,
        q2w, k2w, v2w, s2w, q2b, k2b, v2b, s2b);
    k_init<<<cdiv(n, 256), 256>>>(n);
    k_detect<<<cdiv(e, 256), 256>>>((const int*)ei, e);

    // fork: CSR chain on s2, gemm1 on stream 0 (launch #4 for ncu)
    cudaEventRecord(evA, 0);
    cudaStreamWaitEvent(s2, evA, 0);

    k_mma2<2, true><<<dim3(NTOT1 / 128, mblocks), 256, GSMEM>>>(
        x, nullptr, d_w1hi, d_w1lo, d_b1, d_p1, n, NTOT1, NTOT1);

    k_convhist<<<cdiv(e, 256), 256, 0, s2>>>(ei, e);
    k_scan<<<1, 1024, 0, s2>>>(n);
    k_scatter<<<cdiv(e, 256), 256, 0, s2>>>(e);
    cudaEventRecord(evB, s2);

    // join: edge1 needs gemm1 (stream 0) + CSR (s2)
    cudaStreamWaitEvent(0, evB, 0);
    k_edge1<<<nodeBlocks, 256>>>(b1w, n);

    // ---- layer 2 ----
    k_mma2<4, false><<<dim3(N2P / 128, mblocks), 256, GSMEM>>>(
        d_hhi, d_hlo, d_w2hi, d_w2lo, d_b2, d_p2, n, NTOT2, NTOT2);
    k_edge2<<<nodeBlocks, 256>>>(b2w, out, n);
}

// round 10
// speedup vs baseline: 2.3108x; 1.0256x over previous
#include <cuda_runtime.h>
#include <cuda_bf16.h>
#include <math.h>
#include <stdint.h>

// Problem constants
#define NN   50000
#define EE   800000
#define FIN  128
#define D1   256
#define NOUT 40
#define NTOT1 1024   // packed q|k|v|s layer 1 (4*256)
#define NTOT2 160    // packed q|k|v|s layer 2 (4*40)
#define N2P  256     // padded layer-2 N for GEMM tiles

// ---------------- static scratch ----------------
__device__ __align__(256) float g_p1[(size_t)NN * NTOT1];  // packed q1|k1|v1|s1
__device__ __align__(256) float g_p2[(size_t)NN * NTOT2];  // packed q2|k2|v2|s2

__device__ __align__(256) __nv_bfloat16 g_hhi[(size_t)NN * D1];
__device__ __align__(256) __nv_bfloat16 g_hlo[(size_t)NN * D1];
__device__ __align__(256) __nv_bfloat16 g_w1hi[NTOT1 * FIN];  // [n][k] transposed
__device__ __align__(256) __nv_bfloat16 g_w1lo[NTOT1 * FIN];
__device__ __align__(256) __nv_bfloat16 g_w2hi[N2P * D1];     // [n][k], rows >=160 zero
__device__ __align__(256) __nv_bfloat16 g_w2lo[N2P * D1];
__device__ __align__(256) float g_b1[NTOT1];
__device__ __align__(256) float g_b2[N2P];

__device__ __align__(256) int g_esrc[EE];
__device__ __align__(256) int g_edst[EE];
__device__ int g_is32;
__device__ int g_deg[NN];
__device__ __align__(256) int g_rowptr[NN + 1];
__device__ int g_wp[NN];
__device__ __align__(256) int g_csrsrc[EE];

static inline int cdiv(int a, int b) { return (a + b - 1) / b; }

// ---------------- init + edge dtype detect ----------------
__global__ void k_init(int n) {
    int i = blockIdx.x * blockDim.x + threadIdx.x;
    if (i == 0) g_is32 = 0;
    if (i < n) g_deg[i] = 0;
}
__global__ void k_detect(const int* __restrict__ w, int e) {
    int i = blockIdx.x * blockDim.x + threadIdx.x;
    if (i < e) { if (w[2 * i + 1] != 0) g_is32 = 1; }
}
// fused convert + degree histogram
__global__ void k_convhist(const void* __restrict__ ei, int e) {
    int i = blockIdx.x * blockDim.x + threadIdx.x;
    if (i >= e) return;
    int s_, d_;
    if (g_is32) {
        const int* p = (const int*)ei;
        s_ = p[i]; d_ = p[e + i];
    } else {
        const long long* p = (const long long*)ei;
        s_ = (int)p[i]; d_ = (int)p[e + i];
    }
    g_esrc[i] = s_;
    g_edst[i] = d_;
    atomicAdd(&g_deg[d_], 1);
}

// ---------------- CSR: warp-shfl scan + scatter ----------------
__global__ void k_scan(int n) {   // single block, 1024 threads
    __shared__ int wsum[32];
    const int tid = threadIdx.x, lane = tid & 31, wid = tid >> 5;
    int carry = 0;
    for (int base = 0; base <= n; base += 1024) {
        int idx = base + tid;
        int v = (idx < n) ? g_deg[idx] : 0;
        int x = v;
        #pragma unroll
        for (int o = 1; o < 32; o <<= 1) {
            int t = __shfl_up_sync(0xffffffffu, x, o);
            if (lane >= o) x += t;
        }
        if (lane == 31) wsum[wid] = x;
        __syncthreads();
        if (wid == 0) {
            int w = wsum[lane];
            #pragma unroll
            for (int o = 1; o < 32; o <<= 1) {
                int t = __shfl_up_sync(0xffffffffu, w, o);
                if (lane >= o) w += t;
            }
            wsum[lane] = w;
        }
        __syncthreads();
        int pre = wid ? wsum[wid - 1] : 0;
        int excl = carry + pre + x - v;
        if (idx <= n) {
            g_rowptr[idx] = excl;
            if (idx < n) g_wp[idx] = excl;
        }
        carry += wsum[31];
        __syncthreads();
    }
}
__global__ void k_scatter(int e) {
    int i = blockIdx.x * blockDim.x + threadIdx.x;
    if (i < e) {
        int pos = atomicAdd(&g_wp[g_edst[i]], 1);
        g_csrsrc[pos] = g_esrc[i];
    }
}

// ---------------- weight packing ----------------
__global__ void k_packw(
    const float* q1w, const float* k1w, const float* v1w, const float* s1w,
    const float* q1b, const float* k1b, const float* v1b, const float* s1b,
    const float* q2w, const float* k2w, const float* v2w, const float* s2w,
    const float* q2b, const float* k2b, const float* v2b, const float* s2b)
{
    const float SC1 = 0.17677669529663687f;   // 1/sqrt(32)
    const float SC2 = 0.15811388300841897f;   // 1/sqrt(40)
    int i = blockIdx.x * blockDim.x + threadIdx.x;
    const int W1 = NTOT1 * FIN, W2 = N2P * D1;
    if (i < W1) {
        int n = i / FIN, k = i % FIN;
        const float* s = (n < 256) ? q1w : (n < 512) ? k1w : (n < 768) ? v1w : s1w;
        float v = s[k * 256 + (n & 255)];
        if (n < 256) v *= SC1;
        __nv_bfloat16 h = __float2bfloat16(v);
        g_w1hi[i] = h;
        g_w1lo[i] = __float2bfloat16(v - __bfloat162float(h));
    } else if (i < W1 + W2) {
        int j = i - W1;
        int n = j / D1, k = j % D1;
        float v = 0.f;
        if (n < NTOT2) {
            const float* s = (n < 40) ? q2w : (n < 80) ? k2w : (n < 120) ? v2w : s2w;
            v = s[k * 40 + (n % 40)];
            if (n < 40) v *= SC2;
        }
        __nv_bfloat16 h = __float2bfloat16(v);
        g_w2hi[j] = h;
        g_w2lo[j] = __float2bfloat16(v - __bfloat162float(h));
    } else if (i < W1 + W2 + NTOT1) {
        int c = i - W1 - W2;
        const float* s = (c < 256) ? q1b : (c < 512) ? k1b : (c < 768) ? v1b : s1b;
        float v = s[c & 255];
        if (c < 256) v *= SC1;
        g_b1[c] = v;
    } else if (i < W1 + W2 + NTOT1 + N2P) {
        int c = i - W1 - W2 - NTOT1;
        float v = 0.f;
        if (c < NTOT2) {
            const float* s = (c < 40) ? q2b : (c < 80) ? k2b : (c < 120) ? v2b : s2b;
            v = s[c % 40];
            if (c < 40) v *= SC2;
        }
        g_b2[c] = v;
    }
}

// ---------------- mma.sync bf16 split GEMM ----------------
__device__ __forceinline__ void mma16816(float* c, const uint32_t* a, const uint32_t* b) {
    asm volatile(
        "mma.sync.aligned.m16n8k16.row.col.f32.bf16.bf16.f32 "
        "{%0,%1,%2,%3}, {%4,%5,%6,%7}, {%8,%9}, {%0,%1,%2,%3};\n"
        : "+f"(c[0]), "+f"(c[1]), "+f"(c[2]), "+f"(c[3])
        : "r"(a[0]), "r"(a[1]), "r"(a[2]), "r"(a[3]), "r"(b[0]), "r"(b[1]));
}
#define LDSM4(r, addr) \
    asm volatile("ldmatrix.sync.aligned.m8n8.x4.shared.b16 {%0,%1,%2,%3}, [%4];" \
        : "=r"((r)[0]), "=r"((r)[1]), "=r"((r)[2]), "=r"((r)[3]) : "r"(addr))
#define CPASYNC16(saddr, gptr) \
    asm volatile("cp.async.cg.shared.global [%0], [%1], 16;" :: "r"(saddr), "l"(gptr))
#define CPASYNC_FENCE() \
    asm volatile("cp.async.commit_group;\n\tcp.async.wait_group 0;" ::: "memory")

__device__ __forceinline__ uint32_t smem_u32(const void* p) {
    uint32_t a;
    asm("{ .reg .u64 t; cvta.to.shared.u64 t, %1; cvt.u32.u64 %0, t; }" : "=r"(a) : "l"(p));
    return a;
}

#define SMSTR 72     // bf16 row stride (64 data + 8 pad); 144B row = 16B-aligned
#define TILEB (128 * SMSTR)

// C[M,*] = A[M,K] @ B^T[N,K] + bias ; 3-term split-bf16 in ONE k-pass.
// cp.async staging for bf16 tiles; AF32: A fp32, converted hi/lo during staging.
template <int KCHUNKS, bool AF32>
__global__ void __launch_bounds__(256, 2) k_mma2(
    const void* __restrict__ Ahi_, const void* __restrict__ Alo_,
    const __nv_bfloat16* __restrict__ Bhi, const __nv_bfloat16* __restrict__ Blo,
    const float* __restrict__ bias, float* __restrict__ C,
    int M, int Nvalid, int ldc)
{
    constexpr int K = KCHUNKS * 64;
    extern __shared__ __nv_bfloat16 smem[];
    __nv_bfloat16* AsH = smem;
    __nv_bfloat16* AsL = smem + TILEB;

    const int tid = threadIdx.x, lane = tid & 31, wid = tid >> 5;
    const int wm = wid & 1, wn = wid >> 1;      // warps 2(M) x 4(N); warp tile 64x32
    const int grp = lane >> 2, thr = lane & 3;
    const int sub = lane >> 3, lr = lane & 7;
    const int m0 = blockIdx.y * 128, n0 = blockIdx.x * 128;

    const uint32_t sAH = smem_u32(smem);
    const uint32_t sAL = sAH + TILEB * 2;
    const uint32_t sBH = sAH + 2 * TILEB * 2;
    const uint32_t sBL = sAH + 3 * TILEB * 2;
    const int rA = wm * 64 + lr + (sub & 1) * 8;
    const int kA = (sub >> 1) * 8;
    const int rB = wn * 32 + (sub >> 1) * 8 + lr;
    const int kB = (sub & 1) * 8;
    const bool active = (n0 + wn * 32) < Nvalid;   // skip MMA for all-padding warps

    float c[4][4][4];
    #pragma unroll
    for (int mt = 0; mt < 4; mt++)
        #pragma unroll
        for (int nt = 0; nt < 4; nt++)
            #pragma unroll
            for (int r = 0; r < 4; r++) c[mt][nt][r] = 0.f;

    for (int kc = 0; kc < KCHUNKS; kc++) {
        const int kk = kc * 64;
        // ---- async-stage B (and A when pre-split) ----
        #pragma unroll
        for (int i = 0; i < 4; i++) {
            int q = tid + i * 256;
            int r = q >> 3, s = q & 7;
            uint32_t soff = (uint32_t)(r * SMSTR + s * 8) * 2;
            CPASYNC16(sBH + soff, &Bhi[(size_t)(n0 + r) * K + kk + s * 8]);
            CPASYNC16(sBL + soff, &Blo[(size_t)(n0 + r) * K + kk + s * 8]);
            if (!AF32) {
                int grow = m0 + r;
                if (grow < M) {
                    const __nv_bfloat16* Ahi = (const __nv_bfloat16*)Ahi_;
                    const __nv_bfloat16* Alo = (const __nv_bfloat16*)Alo_;
                    CPASYNC16(sAH + soff, &Ahi[(size_t)grow * K + kk + s * 8]);
                    CPASYNC16(sAL + soff, &Alo[(size_t)grow * K + kk + s * 8]);
                } else {
                    *(uint4*)&AsH[r * SMSTR + s * 8] = make_uint4(0u, 0u, 0u, 0u);
                    *(uint4*)&AsL[r * SMSTR + s * 8] = make_uint4(0u, 0u, 0u, 0u);
                }
            }
        }
        // ---- A fp32 -> hi/lo convert (overlaps with cp.async traffic) ----
        if (AF32) {
            #pragma unroll
            for (int i = 0; i < 4; i++) {
                int q = tid + i * 256;
                int r = q >> 3, s = q & 7;
                int grow = m0 + r;
                const float* A32 = (const float*)Ahi_;
                float4 a0 = make_float4(0.f, 0.f, 0.f, 0.f), a1 = a0;
                if (grow < M) {
                    a0 = *(const float4*)&A32[(size_t)grow * K + kk + s * 8];
                    a1 = *(const float4*)&A32[(size_t)grow * K + kk + s * 8 + 4];
                }
                float vv[8] = { a0.x, a0.y, a0.z, a0.w, a1.x, a1.y, a1.z, a1.w };
                __nv_bfloat162 ph[4], pl[4];
                #pragma unroll
                for (int j = 0; j < 4; j++) {
                    __nv_bfloat16 h0 = __float2bfloat16(vv[2*j]);
                    __nv_bfloat16 h1 = __float2bfloat16(vv[2*j+1]);
                    ph[j] = __halves2bfloat162(h0, h1);
                    pl[j] = __halves2bfloat162(
                        __float2bfloat16(vv[2*j]   - __bfloat162float(h0)),
                        __float2bfloat16(vv[2*j+1] - __bfloat162float(h1)));
                }
                *(uint4*)&AsH[r * SMSTR + s * 8] = *(uint4*)ph;
                *(uint4*)&AsL[r * SMSTR + s * 8] = *(uint4*)pl;
            }
        }
        CPASYNC_FENCE();
        __syncthreads();

        if (active) {
            #pragma unroll
            for (int ks = 0; ks < 4; ks++) {
                const int kb = ks * 16;
                uint32_t ah[4][4], bh[2][4], t[2][4], al4[4];
                #pragma unroll
                for (int mt = 0; mt < 4; mt++)
                    LDSM4(ah[mt], sAH + ((rA + mt * 16) * SMSTR + kb + kA) * 2);
                #pragma unroll
                for (int p = 0; p < 2; p++)
                    LDSM4(bh[p], sBH + ((rB + p * 16) * SMSTR + kb + kB) * 2);
                #pragma unroll
                for (int mt = 0; mt < 4; mt++)
                    #pragma unroll
                    for (int p = 0; p < 2; p++) {
                        mma16816(c[mt][2 * p],     ah[mt], &bh[p][0]);
                        mma16816(c[mt][2 * p + 1], ah[mt], &bh[p][2]);
                    }
                #pragma unroll
                for (int p = 0; p < 2; p++)
                    LDSM4(t[p], sBL + ((rB + p * 16) * SMSTR + kb + kB) * 2);
                #pragma unroll
                for (int mt = 0; mt < 4; mt++)
                    #pragma unroll
                    for (int p = 0; p < 2; p++) {
                        mma16816(c[mt][2 * p],     ah[mt], &t[p][0]);
                        mma16816(c[mt][2 * p + 1], ah[mt], &t[p][2]);
                    }
                #pragma unroll
                for (int mt = 0; mt < 4; mt++) {
                    LDSM4(al4, sAL + ((rA + mt * 16) * SMSTR + kb + kA) * 2);
                    #pragma unroll
                    for (int p = 0; p < 2; p++) {
                        mma16816(c[mt][2 * p],     al4, &bh[p][0]);
                        mma16816(c[mt][2 * p + 1], al4, &bh[p][2]);
                    }
                }
            }
        }
        __syncthreads();
    }

    #pragma unroll
    for (int mt = 0; mt < 4; mt++) {
        int row = m0 + wm * 64 + mt * 16 + grp;
        #pragma unroll
        for (int nt = 0; nt < 4; nt++) {
            int col = n0 + wn * 32 + nt * 8 + thr * 2;
            if (col >= Nvalid) continue;
            float b0 = bias[col], b1 = bias[col + 1];
            if (row < M)
                *(float2*)&C[(size_t)row * ldc + col] =
                    make_float2(c[mt][nt][0] + b0, c[mt][nt][1] + b1);
            if (row + 8 < M)
                *(float2*)&C[(size_t)(row + 8) * ldc + col] =
                    make_float2(c[mt][nt][2] + b0, c[mt][nt][3] + b1);
        }
    }
}

// ---------------- fused layer-1 edge pass (unrolled x2 gather) ----------------
__global__ void __launch_bounds__(256) k_edge1(const float* __restrict__ bw, int n)
{
    __shared__ float w[3 * D1];
    for (int i = threadIdx.x; i < 3 * D1; i += blockDim.x) w[i] = bw[i];
    __syncthreads();

    int warp = (blockIdx.x * blockDim.x + threadIdx.x) >> 5;
    int lane = threadIdx.x & 31;
    if (warp >= n) return;
    int s0 = g_rowptr[warp], s1 = g_rowptr[warp + 1];

    const float* prow = g_p1 + (size_t)warp * NTOT1;
    float4 qa = *(const float4*)(prow + lane * 8);
    float4 qb = *(const float4*)(prow + lane * 8 + 4);

    float a0x=0,a0y=0,a0z=0,a0w=0, a1x=0,a1y=0,a1z=0,a1w=0;
    float asum = 0.f;
    int s = s0;
    for (; s + 1 < s1; s += 2) {
        int src0 = g_csrsrc[s], src1 = g_csrsrc[s + 1];
        const float* b0p = g_p1 + (size_t)src0 * NTOT1;
        const float* b1p = g_p1 + (size_t)src1 * NTOT1;
        float4 ka0 = *(const float4*)(b0p + 256 + lane * 8);
        float4 kb0 = *(const float4*)(b0p + 256 + lane * 8 + 4);
        float4 ka1 = *(const float4*)(b1p + 256 + lane * 8);
        float4 kb1 = *(const float4*)(b1p + 256 + lane * 8 + 4);
        float4 v00 = *(const float4*)(b0p + 512 + lane * 8);
        float4 v01 = *(const float4*)(b0p + 512 + lane * 8 + 4);
        float4 v10 = *(const float4*)(b1p + 512 + lane * 8);
        float4 v11 = *(const float4*)(b1p + 512 + lane * 8 + 4);

        float p0 = qa.x*ka0.x + qa.y*ka0.y + qa.z*ka0.z + qa.w*ka0.w
                 + qb.x*kb0.x + qb.y*kb0.y + qb.z*kb0.z + qb.w*kb0.w;
        float p1 = qa.x*ka1.x + qa.y*ka1.y + qa.z*ka1.z + qa.w*ka1.w
                 + qb.x*kb1.x + qb.y*kb1.y + qb.z*kb1.z + qb.w*kb1.w;
        p0 += __shfl_xor_sync(0xffffffffu, p0, 1);
        p0 += __shfl_xor_sync(0xffffffffu, p0, 2);
        p1 += __shfl_xor_sync(0xffffffffu, p1, 1);
        p1 += __shfl_xor_sync(0xffffffffu, p1, 2);
        float e0 = expf(p0), e1 = expf(p1);   // q pre-scaled by 1/sqrt(32)
        asum += e0 + e1;
        a0x = fmaf(e0, v00.x, a0x); a0y = fmaf(e0, v00.y, a0y);
        a0z = fmaf(e0, v00.z, a0z); a0w = fmaf(e0, v00.w, a0w);
        a1x = fmaf(e0, v01.x, a1x); a1y = fmaf(e0, v01.y, a1y);
        a1z = fmaf(e0, v01.z, a1z); a1w = fmaf(e0, v01.w, a1w);
        a0x = fmaf(e1, v10.x, a0x); a0y = fmaf(e1, v10.y, a0y);
        a0z = fmaf(e1, v10.z, a0z); a0w = fmaf(e1, v10.w, a0w);
        a1x = fmaf(e1, v11.x, a1x); a1y = fmaf(e1, v11.y, a1y);
        a1z = fmaf(e1, v11.z, a1z); a1w = fmaf(e1, v11.w, a1w);
    }
    if (s < s1) {
        int src = g_csrsrc[s];
        const float* base = g_p1 + (size_t)src * NTOT1;
        float4 ka = *(const float4*)(base + 256 + lane * 8);
        float4 kb = *(const float4*)(base + 256 + lane * 8 + 4);
        float4 v0 = *(const float4*)(base + 512 + lane * 8);
        float4 v1 = *(const float4*)(base + 512 + lane * 8 + 4);
        float p = qa.x*ka.x + qa.y*ka.y + qa.z*ka.z + qa.w*ka.w
                + qb.x*kb.x + qb.y*kb.y + qb.z*kb.z + qb.w*kb.w;
        p += __shfl_xor_sync(0xffffffffu, p, 1);
        p += __shfl_xor_sync(0xffffffffu, p, 2);
        float e = expf(p);
        asum += e;
        a0x = fmaf(e, v0.x, a0x); a0y = fmaf(e, v0.y, a0y);
        a0z = fmaf(e, v0.z, a0z); a0w = fmaf(e, v0.w, a0w);
        a1x = fmaf(e, v1.x, a1x); a1y = fmaf(e, v1.y, a1y);
        a1z = fmaf(e, v1.z, a1z); a1w = fmaf(e, v1.w, a1w);
    }
    float inv = (s1 > s0) ? 1.0f / asum : 0.f;
    float o[8] = { a0x*inv, a0y*inv, a0z*inv, a0w*inv, a1x*inv, a1y*inv, a1z*inv, a1w*inv };

    float4 sa = *(const float4*)(prow + 768 + lane * 8);
    float4 sbv = *(const float4*)(prow + 768 + lane * 8 + 4);
    float sk[8] = { sa.x, sa.y, sa.z, sa.w, sbv.x, sbv.y, sbv.z, sbv.w };

    float g = 0.f;
    #pragma unroll
    for (int j = 0; j < 8; j++) {
        int ccol = lane * 8 + j;
        g += o[j] * w[ccol] + sk[j] * w[D1 + ccol] + (o[j] - sk[j]) * w[2 * D1 + ccol];
    }
    #pragma unroll
    for (int off = 16; off >= 1; off >>= 1) g += __shfl_xor_sync(0xffffffffu, g, off);
    float beta = 1.0f / (1.0f + expf(-g));

    __nv_bfloat162 ph[4], pl[4];
    #pragma unroll
    for (int j = 0; j < 4; j++) {
        float v0 = beta * sk[2*j]   + (1.0f - beta) * o[2*j];
        float v1 = beta * sk[2*j+1] + (1.0f - beta) * o[2*j+1];
        v0 = (v0 > 0.f) ? v0 : (expf(v0) - 1.0f);   // ELU
        v1 = (v1 > 0.f) ? v1 : (expf(v1) - 1.0f);
        __nv_bfloat16 h0 = __float2bfloat16(v0), h1 = __float2bfloat16(v1);
        ph[j] = __halves2bfloat162(h0, h1);
        pl[j] = __halves2bfloat162(__float2bfloat16(v0 - __bfloat162float(h0)),
                                   __float2bfloat16(v1 - __bfloat162float(h1)));
    }
    *(uint4*)&g_hhi[(size_t)warp * D1 + lane * 8] = *(uint4*)ph;
    *(uint4*)&g_hlo[(size_t)warp * D1 + lane * 8] = *(uint4*)pl;
}

// ---------------- fused layer-2 edge pass (unrolled x2 gather) ----------------
__global__ void __launch_bounds__(256) k_edge2(const float* __restrict__ bw,
                                               float* __restrict__ out, int n)
{
    __shared__ float w[3 * NOUT];
    for (int i = threadIdx.x; i < 3 * NOUT; i += blockDim.x) w[i] = bw[i];
    __syncthreads();

    int warp = (blockIdx.x * blockDim.x + threadIdx.x) >> 5;
    int lane = threadIdx.x & 31;
    if (warp >= n) return;
    int s0 = g_rowptr[warp], s1 = g_rowptr[warp + 1];

    const float* prow = g_p2 + (size_t)warp * NTOT2;
    float q0 = 0.f, q1 = 0.f;
    if (lane < 20) {
        float2 qq = *(const float2*)(prow + lane * 2);
        q0 = qq.x; q1 = qq.y;
    }
    float acc0 = 0.f, acc1 = 0.f, asum = 0.f;
    int s = s0;
    for (; s + 1 < s1; s += 2) {
        int src0 = g_csrsrc[s], src1 = g_csrsrc[s + 1];
        const float* b0p = g_p2 + (size_t)src0 * NTOT2;
        const float* b1p = g_p2 + (size_t)src1 * NTOT2;
        float p0 = 0.f, p1 = 0.f;
        float v00 = 0.f, v01 = 0.f, v10 = 0.f, v11 = 0.f;
        if (lane < 20) {
            float2 k0 = *(const float2*)(b0p + 40 + lane * 2);
            float2 k1 = *(const float2*)(b1p + 40 + lane * 2);
            float2 w0 = *(const float2*)(b0p + 80 + lane * 2);
            float2 w1 = *(const float2*)(b1p + 80 + lane * 2);
            p0 = q0 * k0.x + q1 * k0.y;
            p1 = q0 * k1.x + q1 * k1.y;
            v00 = w0.x; v01 = w0.y; v10 = w1.x; v11 = w1.y;
        }
        #pragma unroll
        for (int off = 16; off >= 1; off >>= 1) {
            p0 += __shfl_xor_sync(0xffffffffu, p0, off);
            p1 += __shfl_xor_sync(0xffffffffu, p1, off);
        }
        float e0 = expf(p0), e1 = expf(p1);   // q pre-scaled by 1/sqrt(40)
        asum += e0 + e1;
        acc0 = fmaf(e0, v00, acc0); acc1 = fmaf(e0, v01, acc1);
        acc0 = fmaf(e1, v10, acc0); acc1 = fmaf(e1, v11, acc1);
    }
    if (s < s1) {
        int src = g_csrsrc[s];
        const float* base = g_p2 + (size_t)src * NTOT2;
        float p = 0.f, v0 = 0.f, v1 = 0.f;
        if (lane < 20) {
            float2 kk = *(const float2*)(base + 40 + lane * 2);
            p = q0 * kk.x + q1 * kk.y;
            float2 vv = *(const float2*)(base + 80 + lane * 2);
            v0 = vv.x; v1 = vv.y;
        }
        #pragma unroll
        for (int off = 16; off >= 1; off >>= 1) p += __shfl_xor_sync(0xffffffffu, p, off);
        float e = expf(p);
        asum += e;
        acc0 = fmaf(e, v0, acc0);
        acc1 = fmaf(e, v1, acc1);
    }
    float inv = (s1 > s0) ? 1.0f / asum : 0.f;
    float o0 = acc0 * inv, o1 = acc1 * inv;

    float sk0 = 0.f, sk1 = 0.f, g = 0.f;
    if (lane < 20) {
        float2 ss = *(const float2*)(prow + 120 + lane * 2);
        sk0 = ss.x; sk1 = ss.y;
        int ccol = lane * 2;
        g = o0 * w[ccol]     + sk0 * w[NOUT + ccol]     + (o0 - sk0) * w[2 * NOUT + ccol]
          + o1 * w[ccol + 1] + sk1 * w[NOUT + ccol + 1] + (o1 - sk1) * w[2 * NOUT + ccol + 1];
    }
    #pragma unroll
    for (int off = 16; off >= 1; off >>= 1) g += __shfl_xor_sync(0xffffffffu, g, off);
    float beta = 1.0f / (1.0f + expf(-g));
    if (lane < 20) {
        float r0 = beta * sk0 + (1.0f - beta) * o0;
        float r1 = beta * sk1 + (1.0f - beta) * o1;
        *(float2*)(out + (size_t)warp * NOUT + lane * 2) = make_float2(r0, r1);
    }
}

// ---------------- launch ----------------
extern "C" void kernel_launch(void* const* d_in, const int* in_sizes, int n_in,
                              void* d_out, int out_size)
{
    const float* x = (const float*)d_in[0];
    const void* ei = d_in[1];
    const float* q1w = (const float*)d_in[2];
    const float* q1b = (const float*)d_in[3];
    const float* k1w = (const float*)d_in[4];
    const float* k1b = (const float*)d_in[5];
    const float* v1w = (const float*)d_in[6];
    const float* v1b = (const float*)d_in[7];
    const float* s1w = (const float*)d_in[8];
    const float* s1b = (const float*)d_in[9];
    const float* b1w = (const float*)d_in[10];
    const float* q2w = (const float*)d_in[11];
    const float* q2b = (const float*)d_in[12];
    const float* k2w = (const float*)d_in[13];
    const float* k2b = (const float*)d_in[14];
    const float* v2w = (const float*)d_in[15];
    const float* v2b = (const float*)d_in[16];
    const float* s2w = (const float*)d_in[17];
    const float* s2b = (const float*)d_in[18];
    const float* b2w = (const float*)d_in[19];
    float* out = (float*)d_out;

    const int n = in_sizes[0] / FIN;   // 50000
    const int e = in_sizes[1] / 2;     // 800000

    float* d_p1; cudaGetSymbolAddress((void**)&d_p1, g_p1);
    float* d_p2; cudaGetSymbolAddress((void**)&d_p2, g_p2);
    __nv_bfloat16 *d_hhi, *d_hlo, *d_w1hi, *d_w1lo, *d_w2hi, *d_w2lo;
    cudaGetSymbolAddress((void**)&d_hhi, g_hhi);
    cudaGetSymbolAddress((void**)&d_hlo, g_hlo);
    cudaGetSymbolAddress((void**)&d_w1hi, g_w1hi);
    cudaGetSymbolAddress((void**)&d_w1lo, g_w1lo);
    cudaGetSymbolAddress((void**)&d_w2hi, g_w2hi);
    cudaGetSymbolAddress((void**)&d_w2lo, g_w2lo);
    float *d_b1, *d_b2;
    cudaGetSymbolAddress((void**)&d_b1, g_b1);
    cudaGetSymbolAddress((void**)&d_b2, g_b2);

    static cudaStream_t s2 = 0;
    static cudaEvent_t evA = 0, evB = 0;
    if (!s2)  cudaStreamCreateWithFlags(&s2, cudaStreamNonBlocking);
    if (!evA) cudaEventCreateWithFlags(&evA, cudaEventDisableTiming);
    if (!evB) cudaEventCreateWithFlags(&evB, cudaEventDisableTiming);

    const int GSMEM = 4 * TILEB * 2;  // 73728 B
    cudaFuncSetAttribute((const void*)k_mma2<2, true>,  cudaFuncAttributeMaxDynamicSharedMemorySize, GSMEM);
    cudaFuncSetAttribute((const void*)k_mma2<4, false>, cudaFuncAttributeMaxDynamicSharedMemorySize, GSMEM);

    const int mblocks = cdiv(n, 128);
    const int nodeBlocks = cdiv(n * 32, 256);

    // fork immediately: CSR chain (no deps on main-stream work)
    cudaEventRecord(evA, 0);
    cudaStreamWaitEvent(s2, evA, 0);

    k_init<<<cdiv(n, 256), 256, 0, s2>>>(n);                       // #1
    k_detect<<<cdiv(e, 256), 256, 0, s2>>>((const int*)ei, e);     // #2
    const int packTotal = NTOT1 * FIN + N2P * D1 + NTOT1 + N2P;
    k_packw<<<cdiv(packTotal, 256), 256>>>(                        // #3 (main)
        q1w, k1w, v1w, s1w, q1b, k1b, v1b, s1b,
        q2w, k2w, v2w, s2w, q2b, k2b, v2b, s2b);
    k_mma2<2, true><<<dim3(NTOT1 / 128, mblocks), 256, GSMEM>>>(   // #4 (main)
        x, nullptr, d_w1hi, d_w1lo, d_b1, d_p1, n, NTOT1, NTOT1);

    k_convhist<<<cdiv(e, 256), 256, 0, s2>>>(ei, e);               // #5
    k_scan<<<1, 1024, 0, s2>>>(n);                                 // #6
    k_scatter<<<cdiv(e, 256), 256, 0, s2>>>(e);                    // #7
    cudaEventRecord(evB, s2);

    // join: edge1 needs gemm1 (main) + CSR (s2)
    cudaStreamWaitEvent(0, evB, 0);
    k_edge1<<<nodeBlocks, 256>>>(b1w, n);

    // ---- layer 2 ----
    k_mma2<4, false><<<dim3(N2P / 128, mblocks), 256, GSMEM>>>(
        d_hhi, d_hlo, d_w2hi, d_w2lo, d_b2, d_p2, n, NTOT2, NTOT2);
    k_edge2<<<nodeBlocks, 256>>>(b2w, out, n);
}